// round 1
// baseline (speedup 1.0000x reference)
#include <cuda_runtime.h>
#include <cuda_bf16.h>
#include <math.h>

// Problem constants
#define Vv 32000
#define Hh 512
#define Ee 512
#define Bb 64
#define Ss 128
#define Tt 48
#define G4 2048   // 4*H
#define KD 1024   // E+H == 2H

// ---------------- scratch (static device memory; no allocations) -------------
__device__ float g_x[Ss * Bb * Ee];      // [s][b][e] sorted-gathered encoder inputs
__device__ float g_tgt[Tt * Bb * Ee];    // [t][b][e] sorted-gathered decoder inputs
__device__ float g_Xih[Ss * Bb * G4];    // precomputed x @ W_ih_enc^T, [s][b][4H]
__device__ float g_Dpre[Tt * Bb * Hh];   // precomputed tgt @ W_s[:, :E]^T, [t][b][H]
__device__ float g_hs[Bb * Ss * Hh];     // encoder hidden states [b][s][h]
__device__ float g_att1[Bb * Ss];        // tanh(hs @ W_a1^T)
__device__ float g_gates[Bb * G4];       // per-step LSTM gates
__device__ float g_logits[Bb * Vv];      // per-step logits
__device__ float g_ds[Bb * KD];          // [ d | s ]   (gates GEMM A)
__device__ float g_sc[Bb * KD];          // [ s_new | ctx ] (logits GEMM A)
__device__ float g_m[Bb * Hh];           // cell state
__device__ float g_Wcat[G4 * KD];        // [W_ih_dec | W_hh_dec]
__device__ int   g_order[Bb];
__device__ int   g_lens_s[Bb];

// ---------------- helpers ----------------------------------------------------
__device__ __forceinline__ float sigf(float x) { return 1.f / (1.f + expf(-x)); }

// ---------------- sort: stable argsort of -lengths ---------------------------
__global__ void k_sort(const int* __restrict__ lens) {
    // single thread, B=64: stable insertion sort, descending by length
    int idx[Bb];
    for (int i = 0; i < Bb; i++) idx[i] = i;
    for (int i = 1; i < Bb; i++) {
        int v = idx[i];
        int kv = lens[v];
        int j = i - 1;
        while (j >= 0 && lens[idx[j]] < kv) { idx[j + 1] = idx[j]; j--; }
        idx[j + 1] = v;
    }
    for (int i = 0; i < Bb; i++) {
        g_order[i] = idx[i];
        g_lens_s[i] = lens[idx[i]];
    }
}

// ---------------- gathers ----------------------------------------------------
__global__ void k_gather_x(const int* __restrict__ mr, const float* __restrict__ emb) {
    int idx = blockIdx.x * 256 + threadIdx.x;           // over S*B*E
    int e = idx & (Ee - 1);
    int b = (idx >> 9) & (Bb - 1);
    int s = idx >> 15;
    int tok = mr[g_order[b] * Ss + s];
    g_x[idx] = emb[(size_t)tok * Ee + e];
}

__global__ void k_gather_tgt(const int* __restrict__ ref, const float* __restrict__ emb) {
    int idx = blockIdx.x * 256 + threadIdx.x;           // over T*B*E
    int e = idx & (Ee - 1);
    int b = (idx >> 9) & (Bb - 1);
    int t = idx >> 15;
    int tok = ref[g_order[b] * Tt + t];
    g_tgt[idx] = emb[(size_t)tok * Ee + e];
}

__global__ void k_wcat(const float* __restrict__ Wih, const float* __restrict__ Whh) {
    int idx = blockIdx.x * 256 + threadIdx.x;           // over 2048*1024
    int r = idx >> 10, c = idx & 1023;
    g_Wcat[idx] = (c < Hh) ? Wih[r * Hh + c] : Whh[r * Hh + (c - Hh)];
}

__global__ void k_init() {
    int idx = blockIdx.x * 256 + threadIdx.x;
    if (idx < Bb * KD) g_ds[idx] = 0.f;
    int j = idx - Bb * KD;
    if (j >= 0 && j < Bb * Hh) g_m[j] = 0.f;
}

// ---------------- big tiled SGEMM: C = A(MxK) * B(NxK)^T (+Add) --------------
// BM=64, BN=128, BK=16, 256 threads, 4x8 per thread. All dims divide evenly.
__global__ __launch_bounds__(256) void sgemm(
    int M, int N, int K,
    const float* __restrict__ A, int lda,
    const float* __restrict__ Bm, int ldb,
    const float* __restrict__ Add, int ldadd,
    float* __restrict__ C, int ldc)
{
    __shared__ float As[16][64];
    __shared__ float Bs[16][128];
    const int bm = blockIdx.y * 64;
    const int bn = blockIdx.x * 128;
    const int tid = threadIdx.x;
    const int ty = tid >> 4;      // 0..15  -> M sub-tile (4 rows)
    const int tx = tid & 15;      // 0..15  -> N sub-tile (8 cols)

    float acc[4][8];
#pragma unroll
    for (int i = 0; i < 4; i++)
#pragma unroll
        for (int j = 0; j < 8; j++) acc[i][j] = 0.f;

    for (int k0 = 0; k0 < K; k0 += 16) {
        {   // A tile: 64x16 floats = 256 float4
            int r = tid >> 2, c4 = (tid & 3) * 4;
            float4 v = *(const float4*)(A + (size_t)(bm + r) * lda + k0 + c4);
            As[c4 + 0][r] = v.x; As[c4 + 1][r] = v.y;
            As[c4 + 2][r] = v.z; As[c4 + 3][r] = v.w;
        }
#pragma unroll
        for (int l = 0; l < 2; l++) {   // B tile: 128x16 = 512 float4
            int i = tid + l * 256;
            int r = i >> 2, c4 = (i & 3) * 4;
            float4 v = *(const float4*)(Bm + (size_t)(bn + r) * ldb + k0 + c4);
            Bs[c4 + 0][r] = v.x; Bs[c4 + 1][r] = v.y;
            Bs[c4 + 2][r] = v.z; Bs[c4 + 3][r] = v.w;
        }
        __syncthreads();
#pragma unroll
        for (int k = 0; k < 16; k++) {
            float a[4], b[8];
            *(float4*)a       = *(const float4*)&As[k][ty * 4];
            *(float4*)b       = *(const float4*)&Bs[k][tx * 8];
            *(float4*)(b + 4) = *(const float4*)&Bs[k][tx * 8 + 4];
#pragma unroll
            for (int i = 0; i < 4; i++)
#pragma unroll
                for (int j = 0; j < 8; j++) acc[i][j] = fmaf(a[i], b[j], acc[i][j]);
        }
        __syncthreads();
    }
#pragma unroll
    for (int i = 0; i < 4; i++) {
        int m = bm + ty * 4 + i;
#pragma unroll
        for (int j = 0; j < 8; j++) {
            int n = bn + tx * 8 + j;
            float v = acc[i][j];
            if (Add) v += Add[(size_t)m * ldadd + n];
            C[(size_t)m * ldc + n] = v;
        }
    }
}

// ---------------- skinny GEMM: warp computes 4 consecutive n for one m -------
__global__ __launch_bounds__(256) void wgemm(
    int M, int N, int K,
    const float* __restrict__ A, int lda,
    const float* __restrict__ Bm, int ldb,
    const float* __restrict__ Add, int ldadd,
    float* __restrict__ C, int ldc)
{
    int w = blockIdx.x * 8 + (threadIdx.x >> 5);
    int lane = threadIdx.x & 31;
    int nquads = N >> 2;
    if (w >= M * nquads) return;
    int m = w / nquads;
    int n0 = (w - m * nquads) * 4;

    float acc0 = 0.f, acc1 = 0.f, acc2 = 0.f, acc3 = 0.f;
    const float* Ar = A + (size_t)m * lda;
    const float* B0 = Bm + (size_t)(n0 + 0) * ldb;
    const float* B1 = Bm + (size_t)(n0 + 1) * ldb;
    const float* B2 = Bm + (size_t)(n0 + 2) * ldb;
    const float* B3 = Bm + (size_t)(n0 + 3) * ldb;
    for (int k = lane * 4; k < K; k += 128) {
        float4 av = *(const float4*)(Ar + k);
        float4 b;
        b = *(const float4*)(B0 + k); acc0 += av.x*b.x + av.y*b.y + av.z*b.z + av.w*b.w;
        b = *(const float4*)(B1 + k); acc1 += av.x*b.x + av.y*b.y + av.z*b.z + av.w*b.w;
        b = *(const float4*)(B2 + k); acc2 += av.x*b.x + av.y*b.y + av.z*b.z + av.w*b.w;
        b = *(const float4*)(B3 + k); acc3 += av.x*b.x + av.y*b.y + av.z*b.z + av.w*b.w;
    }
#pragma unroll
    for (int off = 16; off; off >>= 1) {
        acc0 += __shfl_down_sync(0xffffffffu, acc0, off);
        acc1 += __shfl_down_sync(0xffffffffu, acc1, off);
        acc2 += __shfl_down_sync(0xffffffffu, acc2, off);
        acc3 += __shfl_down_sync(0xffffffffu, acc3, off);
    }
    if (lane == 0) {
        float v0 = acc0, v1 = acc1, v2 = acc2, v3 = acc3;
        if (Add) {
            const float* ad = Add + (size_t)m * ldadd + n0;
            v0 += ad[0]; v1 += ad[1]; v2 += ad[2]; v3 += ad[3];
        }
        float* cp = C + (size_t)m * ldc + n0;
        cp[0] = v0; cp[1] = v1; cp[2] = v2; cp[3] = v3;
    }
}

// ---------------- encoder LSTM elementwise (with packed-seq semantics) -------
__global__ void k_lstm_enc(int t) {
    int idx = blockIdx.x * 256 + threadIdx.x;   // over B*H
    int b = idx >> 9, h = idx & (Hh - 1);
    const float* gg = g_gates + b * G4;
    float ig = sigf(gg[h]);
    float fg = sigf(gg[Hh + h]);
    float gd = tanhf(gg[2 * Hh + h]);
    float og = sigf(gg[3 * Hh + h]);
    float c_old = g_m[idx];
    float c_new = fg * c_old + ig * gd;
    float h_new = og * tanhf(c_new);
    bool valid = t < g_lens_s[b];
    float h_old = g_ds[b * KD + Hh + h];
    g_m[idx] = valid ? c_new : c_old;
    g_ds[b * KD + Hh + h] = valid ? h_new : h_old;
    g_hs[((size_t)b * Ss + t) * Hh + h] = valid ? h_new : 0.f;
}

// ---------------- decoder LSTM elementwise ------------------------------------
__global__ void k_lstm_dec() {
    int idx = blockIdx.x * 256 + threadIdx.x;   // over B*H
    int b = idx >> 9, h = idx & (Hh - 1);
    const float* gg = g_gates + b * G4;
    float ig = sigf(gg[h]);
    float fg = sigf(gg[Hh + h]);
    float gd = tanhf(gg[2 * Hh + h]);
    float og = sigf(gg[3 * Hh + h]);
    float c_new = fg * g_m[idx] + ig * gd;
    float h_new = og * tanhf(c_new);
    g_m[idx] = c_new;
    g_sc[b * KD + h] = h_new;        // s_new for logits A
    g_ds[b * KD + Hh + h] = h_new;   // s for next step's gates/attention
}

// ---------------- att1 = tanh(hs @ W_a1^T) ------------------------------------
__global__ __launch_bounds__(256) void k_att1(const float* __restrict__ Wa1) {
    int w = blockIdx.x * 8 + (threadIdx.x >> 5);   // over B*S warps
    int lane = threadIdx.x & 31;
    int b = w >> 7, s = w & (Ss - 1);
    float acc = 0.f;
    const float* hr = g_hs + ((size_t)b * Ss + s) * Hh;
    for (int k = lane * 4; k < Hh; k += 128) {
        float4 hv = *(const float4*)(hr + k);
        float4 wv = *(const float4*)(Wa1 + k);
        acc += hv.x * wv.x + hv.y * wv.y + hv.z * wv.z + hv.w * wv.w;
    }
#pragma unroll
    for (int off = 16; off; off >>= 1) acc += __shfl_down_sync(0xffffffffu, acc, off);
    if (lane == 0) g_att1[b * Ss + s] = tanhf(acc);
}

// ---------------- attention: scores + softmax over S + context ---------------
__global__ void k_attn(const float* __restrict__ Wa2, const int* __restrict__ mr_len) {
    int b = blockIdx.x;
    int tid = threadIdx.x;   // 128 threads, S = 128
    __shared__ float red[128];
    __shared__ float alphas[128];
    __shared__ float a_sh;

    // a = tanh(dot(s, W_a2))
    const float* s = g_ds + b * KD + Hh;
    float p = 0.f;
    for (int k = tid; k < Hh; k += 128) p += s[k] * Wa2[k];
    red[tid] = p; __syncthreads();
    for (int off = 64; off; off >>= 1) { if (tid < off) red[tid] += red[tid + off]; __syncthreads(); }
    if (tid == 0) a_sh = tanhf(red[0]);
    __syncthreads();
    float a = a_sh;

    // NOTE: mask uses UNSORTED mr_lengths indexed by the SORTED row (reference bug)
    int len = mr_len[b];
    float e = (tid < len) ? g_att1[b * Ss + tid] * a : -1e9f;

    red[tid] = e; __syncthreads();
    for (int off = 64; off; off >>= 1) { if (tid < off) red[tid] = fmaxf(red[tid], red[tid + off]); __syncthreads(); }
    float mx = red[0]; __syncthreads();
    float ex = expf(e - mx);
    red[tid] = ex; __syncthreads();
    for (int off = 64; off; off >>= 1) { if (tid < off) red[tid] += red[tid + off]; __syncthreads(); }
    alphas[tid] = ex / red[0];
    __syncthreads();

    // ctx[h] = sum_s alpha[s] * hs[b][s][h]  -> into g_sc[:, 512:]
    for (int h = tid; h < Hh; h += 128) {
        float c = 0.f;
        const float* hb = g_hs + (size_t)b * Ss * Hh + h;
#pragma unroll 4
        for (int s2 = 0; s2 < Ss; s2++) c += alphas[s2] * hb[(size_t)s2 * Hh];
        g_sc[b * KD + Hh + h] = c;
    }
}

// ---------------- output softmax over V + desort scatter ---------------------
__global__ void k_softmax_out(float* __restrict__ out, int t) {
    int b = blockIdx.x;
    int tid = threadIdx.x;   // 256 threads
    __shared__ float red[256];
    float* lg = g_logits + (size_t)b * Vv;

    float mx = -1e30f;
    for (int v = tid; v < Vv; v += 256) mx = fmaxf(mx, lg[v]);
    red[tid] = mx; __syncthreads();
    for (int off = 128; off; off >>= 1) { if (tid < off) red[tid] = fmaxf(red[tid], red[tid + off]); __syncthreads(); }
    mx = red[0]; __syncthreads();

    float sum = 0.f;
    for (int v = tid; v < Vv; v += 256) {
        float e = expf(lg[v] - mx);
        lg[v] = e;
        sum += e;
    }
    red[tid] = sum; __syncthreads();
    for (int off = 128; off; off >>= 1) { if (tid < off) red[tid] += red[tid + off]; __syncthreads(); }
    float inv = 1.f / red[0];

    float* dst = out + ((size_t)g_order[b] * Tt + t) * Vv;
    for (int v = tid; v < Vv; v += 256) dst[v] = lg[v] * inv;
}

// ---------------- launch -------------------------------------------------------
extern "C" void kernel_launch(void* const* d_in, const int* in_sizes, int n_in,
                              void* d_out, int out_size) {
    const int*   mr    = (const int*)d_in[0];
    const int*   ref   = (const int*)d_in[1];
    const int*   lens  = (const int*)d_in[2];
    const float* emb   = (const float*)d_in[3];
    const float* Wih_e = (const float*)d_in[4];
    const float* Whh_e = (const float*)d_in[5];
    const float* Wih_d = (const float*)d_in[6];
    const float* Whh_d = (const float*)d_in[7];
    const float* Wy    = (const float*)d_in[8];
    const float* Ws    = (const float*)d_in[9];
    const float* Wa1   = (const float*)d_in[10];
    const float* Wa2   = (const float*)d_in[11];
    float* out = (float*)d_out;

    float *p_x, *p_tgt, *p_Xih, *p_Dpre, *p_gates, *p_logits, *p_ds, *p_sc, *p_Wcat;
    cudaGetSymbolAddress((void**)&p_x,      g_x);
    cudaGetSymbolAddress((void**)&p_tgt,    g_tgt);
    cudaGetSymbolAddress((void**)&p_Xih,    g_Xih);
    cudaGetSymbolAddress((void**)&p_Dpre,   g_Dpre);
    cudaGetSymbolAddress((void**)&p_gates,  g_gates);
    cudaGetSymbolAddress((void**)&p_logits, g_logits);
    cudaGetSymbolAddress((void**)&p_ds,     g_ds);
    cudaGetSymbolAddress((void**)&p_sc,     g_sc);
    cudaGetSymbolAddress((void**)&p_Wcat,   g_Wcat);

    // prep
    k_sort<<<1, 1>>>(lens);
    k_gather_x<<<(Ss * Bb * Ee) / 256, 256>>>(mr, emb);
    k_gather_tgt<<<(Tt * Bb * Ee) / 256, 256>>>(ref, emb);
    k_wcat<<<(G4 * KD) / 256, 256>>>(Wih_d, Whh_d);
    k_init<<<(Bb * KD + Bb * Hh + 255) / 256, 256>>>();

    // Xih = x @ W_ih_enc^T   [S*B, 4H], K=E
    sgemm<<<dim3(G4 / 128, (Ss * Bb) / 64), 256>>>(
        Ss * Bb, G4, Ee, p_x, Ee, Wih_e, Ee, nullptr, 0, p_Xih, G4);

    // Dpre = tgt @ W_s[:, :E]^T   [T*B, H], K=E (ldb = E+H)
    sgemm<<<dim3(Hh / 128, (Tt * Bb) / 64), 256>>>(
        Tt * Bb, Hh, Ee, p_tgt, Ee, Ws, KD, nullptr, 0, p_Dpre, Hh);

    // ---------------- encoder ----------------
    for (int t = 0; t < Ss; t++) {
        // gates = Xih[t] + h @ W_hh_enc^T   [64, 2048], K=512
        int warps = Bb * (G4 / 4);
        wgemm<<<warps / 8, 256>>>(Bb, G4, Hh,
                                  p_ds + Hh, KD, Whh_e, Hh,
                                  p_Xih + (size_t)t * Bb * G4, G4,
                                  p_gates, G4);
        k_lstm_enc<<<(Bb * Hh) / 256, 256>>>(t);
    }

    // att1 = tanh(hs @ W_a1^T)
    k_att1<<<(Bb * Ss) / 8, 256>>>(Wa1);

    // ---------------- decoder ----------------
    for (int t = 0; t < Tt; t++) {
        k_attn<<<Bb, 128>>>(Wa2, lens);

        // d = Dpre[t] + ctx @ W_s[:, E:]^T   [64, 512], K=512
        wgemm<<<(Bb * (Hh / 4)) / 8, 256>>>(Bb, Hh, Hh,
                                            p_sc + Hh, KD, Ws + Ee, KD,
                                            p_Dpre + (size_t)t * Bb * Hh, Hh,
                                            p_ds, KD);

        // gates = [d|s] @ [W_ih_dec|W_hh_dec]^T   [64, 2048], K=1024
        wgemm<<<(Bb * (G4 / 4)) / 8, 256>>>(Bb, G4, KD,
                                            p_ds, KD, p_Wcat, KD,
                                            nullptr, 0, p_gates, G4);

        k_lstm_dec<<<(Bb * Hh) / 256, 256>>>();

        // logits = [s_new|ctx] @ W_y^T   [64, 32000], K=1024
        sgemm<<<dim3(Vv / 128, Bb / 64), 256>>>(
            Bb, Vv, KD, p_sc, KD, Wy, KD, nullptr, 0, p_logits, Vv);

        k_softmax_out<<<Bb, 256>>>(out, t);
    }
}

// round 2
// speedup vs baseline: 1.4877x; 1.4877x over previous
#include <cuda_runtime.h>
#include <cuda_bf16.h>
#include <math.h>

// Problem constants
#define Vv 32000
#define Hh 512
#define Ee 512
#define Bb 64
#define Ss 128
#define Tt 48
#define G4 2048   // 4*H
#define KD 1024   // E+H == 2H

// ---------------- scratch (static device memory; no allocations) -------------
__device__ float g_Xih[Ss * Bb * G4];    // x @ W_ih_enc^T, [s][b][4H]
__device__ float g_Dpre[Tt * Bb * Hh];   // tgt @ W_s[:, :E]^T, [t][b][H]
__device__ float g_hs[Bb * Ss * Hh];     // encoder hidden states [b][s][h]
__device__ float g_att1[Bb * Ss];        // tanh(hs @ W_a1^T)
__device__ float g_gates[Bb * G4];       // per-step LSTM gates
__device__ float g_logits[Bb * Vv];      // per-step logits
__device__ float g_ds[Bb * KD];          // fp32 [ d | s ] (s read by attn)
__device__ float g_sc[Bb * KD];          // fp32 [ . | ctx ] (ctx read by dgemm)
__device__ float g_m[Bb * Hh];           // cell state
__device__ int   g_order[Bb];
__device__ int   g_lens_s[Bb];
__device__ float g_smax[Bb * 8];
__device__ float g_ssum[Bb * 8];

// ---- packed bf16 split fragment buffers ----
// A layout: [mg][kg][lane][8] u32  (regs 0..3 = hi a0..a3, 4..7 = lo)
// B layout: [ng][kg][lane][4] u32  (hi0,hi1,lo0,lo1)
__device__ unsigned g_WyP [4000u * 64 * 32 * 4];   // Wy    N=32000 K=1024
__device__ unsigned g_WcatP[256u * 64 * 32 * 4];   // [Wih_d|Whh_d] N=2048 K=1024
__device__ unsigned g_WhhEP[256u * 32 * 32 * 4];   // Whh_enc N=2048 K=512
__device__ unsigned g_WihEP[256u * 32 * 32 * 4];   // Wih_enc N=2048 K=512
__device__ unsigned g_WsEP [ 64u * 32 * 32 * 4];   // Ws[:, :512] N=512 K=512
__device__ unsigned g_xP  [512u * 32 * 32 * 8];    // x    M=8192 K=512
__device__ unsigned g_tgtP[192u * 32 * 32 * 8];    // tgt  M=3072 K=512
__device__ unsigned g_hP  [  4u * 32 * 32 * 8];    // enc h M=64 K=512
__device__ unsigned g_dsP [  4u * 64 * 32 * 8];    // [d|s] M=64 K=1024
__device__ unsigned g_scP [  4u * 64 * 32 * 8];    // [s_new|ctx] M=64 K=1024

// ---------------- helpers ----------------------------------------------------
__device__ __forceinline__ float sigf(float x) { return 1.f / (1.f + expf(-x)); }

__device__ __forceinline__ unsigned short f2bf(float v) {
    __nv_bfloat16 h = __float2bfloat16(v);
    return __bfloat16_as_ushort(h);
}

// write one fp32 element (m,k) of an A matrix into split-bf16 fragment layout
__device__ __forceinline__ void pack_elem(unsigned* dst, int KG, int m, int k, float v) {
    int mg = m >> 4, ri = m & 15, kg = k >> 4, c = k & 15;
    int lane = ((ri & 7) << 2) + ((c & 7) >> 1);
    int reg  = (ri >> 3) + ((c >> 3) << 1);
    size_t base = (((size_t)mg * KG + kg) * 32 + lane) * 8 + reg;
    unsigned short hb = f2bf(v);
    float r = v - __bfloat162float(__ushort_as_bfloat16(hb));
    unsigned short lb = f2bf(r);
    ((unsigned short*)(dst + base))[c & 1] = hb;
    ((unsigned short*)(dst + base + 4))[c & 1] = lb;
}

__device__ __forceinline__ void mma16816(float* c,
    unsigned a0, unsigned a1, unsigned a2, unsigned a3,
    unsigned b0, unsigned b1)
{
    asm volatile(
        "mma.sync.aligned.m16n8k16.row.col.f32.bf16.bf16.f32 "
        "{%0,%1,%2,%3}, {%4,%5,%6,%7}, {%8,%9}, {%0,%1,%2,%3};"
        : "+f"(c[0]), "+f"(c[1]), "+f"(c[2]), "+f"(c[3])
        : "r"(a0), "r"(a1), "r"(a2), "r"(a3), "r"(b0), "r"(b1));
}

// ---------------- sort: stable argsort of -lengths ---------------------------
__global__ void k_sort(const int* __restrict__ lens) {
    int idx[Bb];
    for (int i = 0; i < Bb; i++) idx[i] = i;
    for (int i = 1; i < Bb; i++) {
        int v = idx[i];
        int kv = lens[v];
        int j = i - 1;
        while (j >= 0 && lens[idx[j]] < kv) { idx[j + 1] = idx[j]; j--; }
        idx[j + 1] = v;
    }
    for (int i = 0; i < Bb; i++) {
        g_order[i] = idx[i];
        g_lens_s[i] = lens[idx[i]];
    }
}

// ---------------- gathers (write directly into packed A layout) --------------
__global__ void k_gather_x(const int* __restrict__ mr, const float* __restrict__ emb) {
    int idx = blockIdx.x * 256 + threadIdx.x;           // over S*B*E
    int e = idx & (Ee - 1);
    int b = (idx >> 9) & (Bb - 1);
    int s = idx >> 15;
    int tok = mr[g_order[b] * Ss + s];
    float v = emb[(size_t)tok * Ee + e];
    pack_elem(g_xP, 32, s * Bb + b, e, v);
}

__global__ void k_gather_tgt(const int* __restrict__ ref, const float* __restrict__ emb) {
    int idx = blockIdx.x * 256 + threadIdx.x;           // over T*B*E
    int e = idx & (Ee - 1);
    int b = (idx >> 9) & (Bb - 1);
    int t = idx >> 15;
    int tok = ref[g_order[b] * Tt + t];
    float v = emb[(size_t)tok * Ee + e];
    pack_elem(g_tgtP, 32, t * Bb + b, e, v);
}

__global__ void k_init() {
    int idx = blockIdx.x * 256 + threadIdx.x;
    if (idx < Bb * KD) g_ds[idx] = 0.f;
    if (idx < Bb * Hh) g_m[idx] = 0.f;
    if (idx < 4 * 32 * 32 * 8) g_hP[idx] = 0u;
}

// ---------------- pack B matrices into fragment layout ------------------------
// src1 provides k < ksplit (row stride ld1); src2 (optional) provides k >= ksplit
__global__ void k_packB(const float* __restrict__ s1, int ld1,
                        const float* __restrict__ s2, int ksplit,
                        unsigned* __restrict__ dst, int KG)
{
    int idx = blockIdx.x * 256 + threadIdx.x;  // (ng*KG + kg)*32 + lane
    int lane = idx & 31;
    int kg = (idx >> 5) % KG;
    int ng = idx / (32 * KG);
    int n = ng * 8 + (lane >> 2);
    int k0 = kg * 16 + (lane & 3) * 2;
    float e[4];
    int ks[4] = { k0, k0 + 1, k0 + 8, k0 + 9 };
#pragma unroll
    for (int i = 0; i < 4; i++) {
        int k = ks[i];
        e[i] = (s2 && k >= ksplit) ? s2[(size_t)n * 512 + (k - ksplit)]
                                   : s1[(size_t)n * ld1 + k];
    }
    unsigned short hb[4], lb[4];
#pragma unroll
    for (int i = 0; i < 4; i++) {
        hb[i] = f2bf(e[i]);
        lb[i] = f2bf(e[i] - __bfloat162float(__ushort_as_bfloat16(hb[i])));
    }
    uint4 w;
    w.x = (unsigned)hb[0] | ((unsigned)hb[1] << 16);
    w.y = (unsigned)hb[2] | ((unsigned)hb[3] << 16);
    w.z = (unsigned)lb[0] | ((unsigned)lb[1] << 16);
    w.w = (unsigned)lb[2] | ((unsigned)lb[3] << 16);
    *(uint4*)(dst + (size_t)idx * 4) = w;
}

// ---------------- split-bf16 tensor-core GEMM --------------------------------
// C[M x N] = A * B^T (+ Add). Block tile 64(M) x 64(N), 8 warps.
__global__ __launch_bounds__(256) void mma_gemm(
    const unsigned* __restrict__ AP,
    const unsigned* __restrict__ BP,
    const float* __restrict__ Add, int ldadd,
    float* __restrict__ C, int ldc, int KG)
{
    const int lane = threadIdx.x & 31;
    const int w = threadIdx.x >> 5;
    const int mg = blockIdx.y * 4 + (w & 3);
    const int ngBase = blockIdx.x * 8 + (w >> 2) * 4;

    float acc[4][4];
#pragma unroll
    for (int j = 0; j < 4; j++)
#pragma unroll
        for (int i = 0; i < 4; i++) acc[j][i] = 0.f;

    const unsigned* aPtr = AP + (((size_t)mg * KG) * 32 + lane) * 8;
    const unsigned* bPtr = BP + (((size_t)ngBase * KG) * 32 + lane) * 4;
    const size_t bNg = (size_t)KG * 128;

    for (int kg = 0; kg < KG; kg++) {
        uint4 ah = *(const uint4*)aPtr;
        uint4 al = *(const uint4*)(aPtr + 4);
        aPtr += 256;
#pragma unroll
        for (int j = 0; j < 4; j++) {
            uint4 bb = *(const uint4*)(bPtr + j * bNg);
            mma16816(acc[j], ah.x, ah.y, ah.z, ah.w, bb.x, bb.y);  // hi*hi
            mma16816(acc[j], al.x, al.y, al.z, al.w, bb.x, bb.y);  // lo*hi
            mma16816(acc[j], ah.x, ah.y, ah.z, ah.w, bb.z, bb.w);  // hi*lo
        }
        bPtr += 128;
    }

    const int row = lane >> 2;
    const int col = (lane & 3) * 2;
    const int m0 = mg * 16 + row;
#pragma unroll
    for (int j = 0; j < 4; j++) {
        int n = (ngBase + j) * 8 + col;
        float v00 = acc[j][0], v01 = acc[j][1], v10 = acc[j][2], v11 = acc[j][3];
        if (Add) {
            v00 += Add[(size_t)m0 * ldadd + n];       v01 += Add[(size_t)m0 * ldadd + n + 1];
            v10 += Add[(size_t)(m0 + 8) * ldadd + n]; v11 += Add[(size_t)(m0 + 8) * ldadd + n + 1];
        }
        *(float2*)&C[(size_t)m0 * ldc + n] = make_float2(v00, v01);
        *(float2*)&C[(size_t)(m0 + 8) * ldc + n] = make_float2(v10, v11);
    }
}

// ---------------- d = Dpre[t] + ctx @ Ws[:,512:]^T  (scalar warp GEMM) -------
__global__ __launch_bounds__(256) void k_dgemm(const float* __restrict__ Ws,
                                               const float* __restrict__ Dpre_t)
{
    int w = blockIdx.x * 8 + (threadIdx.x >> 5);   // 64*128 warps
    int lane = threadIdx.x & 31;
    int m = w >> 7;                 // /128
    int n0 = (w & 127) * 4;

    float acc0 = 0.f, acc1 = 0.f, acc2 = 0.f, acc3 = 0.f;
    const float* Ar = g_sc + (size_t)m * KD + Hh;   // ctx
    const float* B0 = Ws + (size_t)(n0 + 0) * KD + Ee;
    const float* B1 = Ws + (size_t)(n0 + 1) * KD + Ee;
    const float* B2 = Ws + (size_t)(n0 + 2) * KD + Ee;
    const float* B3 = Ws + (size_t)(n0 + 3) * KD + Ee;
    for (int k = lane * 4; k < Hh; k += 128) {
        float4 av = *(const float4*)(Ar + k);
        float4 b;
        b = *(const float4*)(B0 + k); acc0 += av.x*b.x + av.y*b.y + av.z*b.z + av.w*b.w;
        b = *(const float4*)(B1 + k); acc1 += av.x*b.x + av.y*b.y + av.z*b.z + av.w*b.w;
        b = *(const float4*)(B2 + k); acc2 += av.x*b.x + av.y*b.y + av.z*b.z + av.w*b.w;
        b = *(const float4*)(B3 + k); acc3 += av.x*b.x + av.y*b.y + av.z*b.z + av.w*b.w;
    }
#pragma unroll
    for (int off = 16; off; off >>= 1) {
        acc0 += __shfl_down_sync(0xffffffffu, acc0, off);
        acc1 += __shfl_down_sync(0xffffffffu, acc1, off);
        acc2 += __shfl_down_sync(0xffffffffu, acc2, off);
        acc3 += __shfl_down_sync(0xffffffffu, acc3, off);
    }
    if (lane == 0) {
        const float* ad = Dpre_t + (size_t)m * Hh + n0;
        float v[4] = { acc0 + ad[0], acc1 + ad[1], acc2 + ad[2], acc3 + ad[3] };
#pragma unroll
        for (int i = 0; i < 4; i++) {
            g_ds[(size_t)m * KD + n0 + i] = v[i];
            pack_elem(g_dsP, 64, m, n0 + i, v[i]);   // d occupies k 0..511
        }
    }
}

// ---------------- encoder LSTM elementwise + packing --------------------------
__global__ void k_lstm_enc(int t) {
    int idx = blockIdx.x * 256 + threadIdx.x;   // over B*H
    int b = idx >> 9, h = idx & (Hh - 1);
    const float* gg = g_gates + b * G4;
    float ig = sigf(gg[h]);
    float fg = sigf(gg[Hh + h]);
    float gd = tanhf(gg[2 * Hh + h]);
    float og = sigf(gg[3 * Hh + h]);
    float c_old = g_m[idx];
    float c_new = fg * c_old + ig * gd;
    float h_new = og * tanhf(c_new);
    bool valid = t < g_lens_s[b];
    float h_old = g_ds[b * KD + Hh + h];
    float hcur = valid ? h_new : h_old;
    g_m[idx] = valid ? c_new : c_old;
    g_ds[b * KD + Hh + h] = hcur;
    g_hs[((size_t)b * Ss + t) * Hh + h] = valid ? h_new : 0.f;
    pack_elem(g_hP, 32, b, h, hcur);           // A for next encoder gates mma
    pack_elem(g_dsP, 64, b, Hh + h, hcur);     // s part of decoder gates A
}

// ---------------- decoder LSTM elementwise + packing --------------------------
__global__ void k_lstm_dec() {
    int idx = blockIdx.x * 256 + threadIdx.x;   // over B*H
    int b = idx >> 9, h = idx & (Hh - 1);
    const float* gg = g_gates + b * G4;
    float ig = sigf(gg[h]);
    float fg = sigf(gg[Hh + h]);
    float gd = tanhf(gg[2 * Hh + h]);
    float og = sigf(gg[3 * Hh + h]);
    float c_new = fg * g_m[idx] + ig * gd;
    float h_new = og * tanhf(c_new);
    g_m[idx] = c_new;
    g_ds[b * KD + Hh + h] = h_new;             // s for next step (attn reads fp32)
    pack_elem(g_scP, 64, b, h, h_new);         // s_new part of logits A
    pack_elem(g_dsP, 64, b, Hh + h, h_new);    // s part of next gates A
}

// ---------------- att1 = tanh(hs @ W_a1^T) ------------------------------------
__global__ __launch_bounds__(256) void k_att1(const float* __restrict__ Wa1) {
    int w = blockIdx.x * 8 + (threadIdx.x >> 5);   // over B*S warps
    int lane = threadIdx.x & 31;
    int b = w >> 7, s = w & (Ss - 1);
    float acc = 0.f;
    const float* hr = g_hs + ((size_t)b * Ss + s) * Hh;
    for (int k = lane * 4; k < Hh; k += 128) {
        float4 hv = *(const float4*)(hr + k);
        float4 wv = *(const float4*)(Wa1 + k);
        acc += hv.x * wv.x + hv.y * wv.y + hv.z * wv.z + hv.w * wv.w;
    }
#pragma unroll
    for (int off = 16; off; off >>= 1) acc += __shfl_down_sync(0xffffffffu, acc, off);
    if (lane == 0) g_att1[b * Ss + s] = tanhf(acc);
}

// ---------------- attention: scores + softmax over S + context ---------------
__global__ void k_attn(const float* __restrict__ Wa2, const int* __restrict__ mr_len) {
    int b = blockIdx.x;
    int tid = threadIdx.x;   // 128 threads, S = 128
    __shared__ float red[128];
    __shared__ float alphas[128];
    __shared__ float a_sh;

    const float* s = g_ds + b * KD + Hh;
    float p = 0.f;
    for (int k = tid; k < Hh; k += 128) p += s[k] * Wa2[k];
    red[tid] = p; __syncthreads();
    for (int off = 64; off; off >>= 1) { if (tid < off) red[tid] += red[tid + off]; __syncthreads(); }
    if (tid == 0) a_sh = tanhf(red[0]);
    __syncthreads();
    float a = a_sh;

    // NOTE: mask uses UNSORTED mr_lengths indexed by the SORTED row (reference bug)
    int len = mr_len[b];
    float e = (tid < len) ? g_att1[b * Ss + tid] * a : -1e9f;

    red[tid] = e; __syncthreads();
    for (int off = 64; off; off >>= 1) { if (tid < off) red[tid] = fmaxf(red[tid], red[tid + off]); __syncthreads(); }
    float mx = red[0]; __syncthreads();
    float ex = expf(e - mx);
    red[tid] = ex; __syncthreads();
    for (int off = 64; off; off >>= 1) { if (tid < off) red[tid] += red[tid + off]; __syncthreads(); }
    alphas[tid] = ex / red[0];
    __syncthreads();

    for (int h = tid; h < Hh; h += 128) {
        float c = 0.f;
        const float* hb = g_hs + (size_t)b * Ss * Hh + h;
#pragma unroll 4
        for (int s2 = 0; s2 < Ss; s2++) c += alphas[s2] * hb[(size_t)s2 * Hh];
        g_sc[b * KD + Hh + h] = c;                 // fp32 ctx for dgemm
        pack_elem(g_scP, 64, b, Hh + h, c);        // ctx part of logits A
    }
}

// ---------------- output softmax (2-pass, saturating MUFU) -------------------
__global__ void k_sm1() {
    int b = blockIdx.x >> 3, ch = blockIdx.x & 7;
    float* lg = g_logits + (size_t)b * Vv + ch * 4000;
    int tid = threadIdx.x;   // 256
    __shared__ float red[256];

    float mx = -1e30f;
    for (int v = tid; v < 4000; v += 256) mx = fmaxf(mx, lg[v]);
    red[tid] = mx; __syncthreads();
    for (int off = 128; off; off >>= 1) { if (tid < off) red[tid] = fmaxf(red[tid], red[tid + off]); __syncthreads(); }
    mx = red[0]; __syncthreads();

    float sum = 0.f;
    for (int v = tid; v < 4000; v += 256) {
        float e = __expf(lg[v] - mx);
        lg[v] = e;
        sum += e;
    }
    red[tid] = sum; __syncthreads();
    for (int off = 128; off; off >>= 1) { if (tid < off) red[tid] += red[tid + off]; __syncthreads(); }
    if (tid == 0) { g_smax[blockIdx.x] = mx; g_ssum[blockIdx.x] = red[0]; }
}

__global__ void k_sm2(float* __restrict__ out, int t) {
    int b = blockIdx.x >> 3, ch = blockIdx.x & 7;
    __shared__ float scale_sh;
    if (threadIdx.x == 0) {
        float gmax = -1e30f;
        for (int i = 0; i < 8; i++) gmax = fmaxf(gmax, g_smax[b * 8 + i]);
        float gsum = 0.f;
        for (int i = 0; i < 8; i++) gsum += g_ssum[b * 8 + i] * __expf(g_smax[b * 8 + i] - gmax);
        scale_sh = __expf(g_smax[b * 8 + ch] - gmax) / gsum;
    }
    __syncthreads();
    float sc = scale_sh;
    const float* lg = g_logits + (size_t)b * Vv + ch * 4000;
    float* dst = out + ((size_t)g_order[b] * Tt + t) * Vv + ch * 4000;
    for (int v = threadIdx.x; v < 4000; v += 256) dst[v] = lg[v] * sc;
}

// ---------------- launch -------------------------------------------------------
extern "C" void kernel_launch(void* const* d_in, const int* in_sizes, int n_in,
                              void* d_out, int out_size) {
    const int*   mr    = (const int*)d_in[0];
    const int*   ref   = (const int*)d_in[1];
    const int*   lens  = (const int*)d_in[2];
    const float* emb   = (const float*)d_in[3];
    const float* Wih_e = (const float*)d_in[4];
    const float* Whh_e = (const float*)d_in[5];
    const float* Wih_d = (const float*)d_in[6];
    const float* Whh_d = (const float*)d_in[7];
    const float* Wy    = (const float*)d_in[8];
    const float* Ws    = (const float*)d_in[9];
    const float* Wa1   = (const float*)d_in[10];
    const float* Wa2   = (const float*)d_in[11];
    float* out = (float*)d_out;

    float *p_Xih, *p_Dpre, *p_gates, *p_logits;
    unsigned *p_WyP, *p_WcatP, *p_WhhEP, *p_WihEP, *p_WsEP, *p_xP, *p_tgtP, *p_hP, *p_dsP, *p_scP;
    cudaGetSymbolAddress((void**)&p_Xih,    g_Xih);
    cudaGetSymbolAddress((void**)&p_Dpre,   g_Dpre);
    cudaGetSymbolAddress((void**)&p_gates,  g_gates);
    cudaGetSymbolAddress((void**)&p_logits, g_logits);
    cudaGetSymbolAddress((void**)&p_WyP,    g_WyP);
    cudaGetSymbolAddress((void**)&p_WcatP,  g_WcatP);
    cudaGetSymbolAddress((void**)&p_WhhEP,  g_WhhEP);
    cudaGetSymbolAddress((void**)&p_WihEP,  g_WihEP);
    cudaGetSymbolAddress((void**)&p_WsEP,   g_WsEP);
    cudaGetSymbolAddress((void**)&p_xP,     g_xP);
    cudaGetSymbolAddress((void**)&p_tgtP,   g_tgtP);
    cudaGetSymbolAddress((void**)&p_hP,     g_hP);
    cudaGetSymbolAddress((void**)&p_dsP,    g_dsP);
    cudaGetSymbolAddress((void**)&p_scP,    g_scP);

    // ---- prep ----
    k_sort<<<1, 1>>>(lens);
    k_gather_x<<<(Ss * Bb * Ee) / 256, 256>>>(mr, emb);
    k_gather_tgt<<<(Tt * Bb * Ee) / 256, 256>>>(ref, emb);
    k_init<<<(Bb * KD + 255) / 256, 256>>>();

    k_packB<<<(4000 * 64 * 32) / 256, 256>>>(Wy, KD, nullptr, 0, p_WyP, 64);
    k_packB<<<(256 * 64 * 32) / 256, 256>>>(Wih_d, Hh, Whh_d, Hh, p_WcatP, 64);
    k_packB<<<(256 * 32 * 32) / 256, 256>>>(Whh_e, Hh, nullptr, 0, p_WhhEP, 32);
    k_packB<<<(256 * 32 * 32) / 256, 256>>>(Wih_e, Hh, nullptr, 0, p_WihEP, 32);
    k_packB<<<(64 * 32 * 32) / 256, 256>>>(Ws, KD, nullptr, 0, p_WsEP, 32);

    // Xih = x @ W_ih_enc^T  [8192 x 2048], K=512
    mma_gemm<<<dim3(G4 / 64, (Ss * Bb) / 64), 256>>>(p_xP, p_WihEP, nullptr, 0, p_Xih, G4, 32);
    // Dpre = tgt @ Ws[:, :E]^T  [3072 x 512], K=512
    mma_gemm<<<dim3(Hh / 64, (Tt * Bb) / 64), 256>>>(p_tgtP, p_WsEP, nullptr, 0, p_Dpre, Hh, 32);

    // ---- encoder ----
    for (int t = 0; t < Ss; t++) {
        mma_gemm<<<dim3(G4 / 64, 1), 256>>>(p_hP, p_WhhEP,
                                            p_Xih + (size_t)t * Bb * G4, G4,
                                            p_gates, G4, 32);
        k_lstm_enc<<<(Bb * Hh) / 256, 256>>>(t);
    }

    k_att1<<<(Bb * Ss) / 8, 256>>>(Wa1);

    // ---- decoder ----
    for (int t = 0; t < Tt; t++) {
        k_attn<<<Bb, 128>>>(Wa2, lens);
        k_dgemm<<<(Bb * 128) / 8, 256>>>(Ws, p_Dpre + (size_t)t * Bb * Hh);
        mma_gemm<<<dim3(G4 / 64, 1), 256>>>(p_dsP, p_WcatP, nullptr, 0, p_gates, G4, 64);
        k_lstm_dec<<<(Bb * Hh) / 256, 256>>>();
        mma_gemm<<<dim3(Vv / 64, 1), 256>>>(p_scP, p_WyP, nullptr, 0, p_logits, Vv, 64);
        k_sm1<<<Bb * 8, 256>>>();
        k_sm2<<<Bb * 8, 256>>>(out, t);
    }
}

// round 3
// speedup vs baseline: 1.7364x; 1.1672x over previous
#include <cuda_runtime.h>
#include <cuda_bf16.h>
#include <math.h>

// Problem constants
#define Vv 32000
#define Hh 512
#define Ee 512
#define Bb 64
#define Ss 128
#define Tt 48
#define G4 2048   // 4*H
#define KD 1024   // E+H == 2H
#define NTILES 250   // logits tiles of 128 cols

// ---------------- scratch (static device memory; no allocations) -------------
__device__ float g_Xih[Ss * Bb * G4];    // x @ W_ih_enc^T, [s][b][4H]
__device__ float g_Gpre[Tt * Bb * G4];   // tgt @ M1^T (y-part of decoder gates)
__device__ float g_hs[Bb * Ss * Hh];     // encoder hidden states [b][s][h]
__device__ float g_att1[Bb * Ss];        // tanh(hs @ W_a1^T)
__device__ float g_gates[Bb * G4];       // per-step LSTM gates
__device__ float g_logits[Bb * Vv];      // per-step logits
__device__ float g_s[Bb * Hh];           // hidden state fp32 (attn reads)
__device__ float g_m[Bb * Hh];           // cell state
__device__ float g_M12[G4 * KD];         // [M1 | M2] = Wih_d @ Ws  (fp32)
__device__ float g_pmax[NTILES * Bb];
__device__ float g_psum[NTILES * Bb];
__device__ int   g_order[Bb];
__device__ int   g_lens_s[Bb];

// grid barrier
__device__ unsigned g_barcnt = 0;
__device__ volatile unsigned g_bargen = 0;

// ---- packed bf16 split fragment buffers ----
// A layout: [mg][kg][lane][8] u32  (regs 0..3 = hi a0..a3, 4..7 = lo)
// B layout: [ng][kg][lane][4] u32  (hi0,hi1,lo0,lo1)
__device__ unsigned g_WyP [4000u * 64 * 32 * 4];   // Wy    N=32000 K=1024
__device__ unsigned g_GcatP[256u * 64 * 32 * 4];   // [M2|Whh_d] N=2048 K=1024
__device__ unsigned g_WhhEP[256u * 32 * 32 * 4];   // Whh_enc N=2048 K=512
__device__ unsigned g_WihEP[256u * 32 * 32 * 4];   // Wih_enc N=2048 K=512
__device__ unsigned g_WsTP [128u * 32 * 32 * 4];   // Ws^T   N=1024 K=512
__device__ unsigned g_M1P  [256u * 32 * 32 * 4];   // M1     N=2048 K=512
__device__ unsigned g_WihdA[128u * 32 * 32 * 8];   // Wih_d A-layout M=2048 K=512
__device__ unsigned g_xP  [512u * 32 * 32 * 8];    // x    M=8192 K=512
__device__ unsigned g_tgtP[192u * 32 * 32 * 8];    // tgt  M=3072 K=512
__device__ unsigned g_hP  [  4u * 32 * 32 * 8];    // enc h M=64 K=512
__device__ unsigned g_gAP [  4u * 64 * 32 * 8];    // [ctx|s] M=64 K=1024 (gates A)
__device__ unsigned g_scP [  4u * 64 * 32 * 8];    // [s_new|ctx] M=64 K=1024 (logits A)

// ---------------- helpers ----------------------------------------------------
__device__ __forceinline__ float sigf(float x) { return 1.f / (1.f + expf(-x)); }

__device__ __forceinline__ unsigned short f2bf(float v) {
    __nv_bfloat16 h = __float2bfloat16(v);
    return __bfloat16_as_ushort(h);
}

// write one fp32 element (m,k) of an A matrix into split-bf16 fragment layout
__device__ __forceinline__ void pack_elem(unsigned* dst, int KG, int m, int k, float v) {
    int mg = m >> 4, ri = m & 15, kg = k >> 4, c = k & 15;
    int lane = ((ri & 7) << 2) + ((c & 7) >> 1);
    int reg  = (ri >> 3) + ((c >> 3) << 1);
    size_t base = (((size_t)mg * KG + kg) * 32 + lane) * 8 + reg;
    unsigned short hb = f2bf(v);
    float r = v - __bfloat162float(__ushort_as_bfloat16(hb));
    unsigned short lb = f2bf(r);
    ((unsigned short*)(dst + base))[c & 1] = hb;
    ((unsigned short*)(dst + base + 4))[c & 1] = lb;
}

__device__ __forceinline__ void mma16816(float* c,
    unsigned a0, unsigned a1, unsigned a2, unsigned a3,
    unsigned b0, unsigned b1)
{
    asm volatile(
        "mma.sync.aligned.m16n8k16.row.col.f32.bf16.bf16.f32 "
        "{%0,%1,%2,%3}, {%4,%5,%6,%7}, {%8,%9}, {%0,%1,%2,%3};"
        : "+f"(c[0]), "+f"(c[1]), "+f"(c[2]), "+f"(c[3])
        : "r"(a0), "r"(a1), "r"(a2), "r"(a3), "r"(b0), "r"(b1));
}

__device__ __forceinline__ void gridsync(unsigned nb) {
    __threadfence();
    __syncthreads();
    if (threadIdx.x == 0) {
        unsigned gen = g_bargen;
        if (atomicAdd(&g_barcnt, 1u) == nb - 1u) {
            g_barcnt = 0;
            __threadfence();
            g_bargen = gen + 1u;
        } else {
            while (g_bargen == gen) { }
        }
    }
    __syncthreads();
    __threadfence();   // invalidate reader L1 (CCTL.IVALL)
}

// ---------------- sort: stable argsort of -lengths ---------------------------
__global__ void k_sort(const int* __restrict__ lens) {
    int idx[Bb];
    for (int i = 0; i < Bb; i++) idx[i] = i;
    for (int i = 1; i < Bb; i++) {
        int v = idx[i];
        int kv = lens[v];
        int j = i - 1;
        while (j >= 0 && lens[idx[j]] < kv) { idx[j + 1] = idx[j]; j--; }
        idx[j + 1] = v;
    }
    for (int i = 0; i < Bb; i++) {
        g_order[i] = idx[i];
        g_lens_s[i] = lens[idx[i]];
    }
}

// ---------------- gathers (write directly into packed A layout) --------------
__global__ void k_gather_x(const int* __restrict__ mr, const float* __restrict__ emb) {
    int idx = blockIdx.x * 256 + threadIdx.x;           // over S*B*E
    int e = idx & (Ee - 1);
    int b = (idx >> 9) & (Bb - 1);
    int s = idx >> 15;
    int tok = mr[g_order[b] * Ss + s];
    float v = emb[(size_t)tok * Ee + e];
    pack_elem(g_xP, 32, s * Bb + b, e, v);
}

__global__ void k_gather_tgt(const int* __restrict__ ref, const float* __restrict__ emb) {
    int idx = blockIdx.x * 256 + threadIdx.x;           // over T*B*E
    int e = idx & (Ee - 1);
    int b = (idx >> 9) & (Bb - 1);
    int t = idx >> 15;
    int tok = ref[g_order[b] * Tt + t];
    float v = emb[(size_t)tok * Ee + e];
    pack_elem(g_tgtP, 32, t * Bb + b, e, v);
}

__global__ void k_init() {
    int idx = blockIdx.x * 256 + threadIdx.x;   // 32768 threads
    g_s[idx] = 0.f;
    g_m[idx] = 0.f;
    g_hP[idx] = 0u;
}

// ---------------- pack A weight (row-major fp32 -> A frag) -------------------
__global__ void k_packAw(const float* __restrict__ src, unsigned* __restrict__ dst, int KG) {
    int idx = blockIdx.x * 256 + threadIdx.x;
    int K = KG * 16;
    int m = idx / K, k = idx - m * K;
    pack_elem(dst, KG, m, k, src[idx]);
}

// ---------------- pack B matrices into fragment layout (general strides) -----
// elem(n,k) = k < ksplit ? s1[n*sN1 + k*sK1] : s2[n*sN2 + (k-ksplit)*sK2]
__global__ void k_packB(const float* __restrict__ s1, long sN1, long sK1,
                        const float* __restrict__ s2, long sN2, long sK2,
                        int ksplit, unsigned* __restrict__ dst, int KG)
{
    int idx = blockIdx.x * 256 + threadIdx.x;  // (ng*KG + kg)*32 + lane
    int lane = idx & 31;
    int kg = (idx >> 5) % KG;
    int ng = idx / (32 * KG);
    int n = ng * 8 + (lane >> 2);
    int k0 = kg * 16 + (lane & 3) * 2;
    float e[4];
    int ks[4] = { k0, k0 + 1, k0 + 8, k0 + 9 };
#pragma unroll
    for (int i = 0; i < 4; i++) {
        int k = ks[i];
        e[i] = (k >= ksplit) ? s2[(size_t)n * sN2 + (size_t)(k - ksplit) * sK2]
                             : s1[(size_t)n * sN1 + (size_t)k * sK1];
    }
    unsigned short hb[4], lb[4];
#pragma unroll
    for (int i = 0; i < 4; i++) {
        hb[i] = f2bf(e[i]);
        lb[i] = f2bf(e[i] - __bfloat162float(__ushort_as_bfloat16(hb[i])));
    }
    uint4 w;
    w.x = (unsigned)hb[0] | ((unsigned)hb[1] << 16);
    w.y = (unsigned)hb[2] | ((unsigned)hb[3] << 16);
    w.z = (unsigned)lb[0] | ((unsigned)lb[1] << 16);
    w.w = (unsigned)lb[2] | ((unsigned)lb[3] << 16);
    *(uint4*)(dst + (size_t)idx * 4) = w;
}

// ---------------- generic split-bf16 tensor-core GEMM ------------------------
// C[M x N] = A * B^T (+ Add). Block tile 64(M) x 64(N), 8 warps.
__global__ __launch_bounds__(256) void mma_gemm(
    const unsigned* __restrict__ AP,
    const unsigned* __restrict__ BP,
    const float* __restrict__ Add, int ldadd,
    float* __restrict__ C, int ldc, int KG)
{
    const int lane = threadIdx.x & 31;
    const int w = threadIdx.x >> 5;
    const int mg = blockIdx.y * 4 + (w & 3);
    const int ngBase = blockIdx.x * 8 + (w >> 2) * 4;

    float acc[4][4];
#pragma unroll
    for (int j = 0; j < 4; j++)
#pragma unroll
        for (int i = 0; i < 4; i++) acc[j][i] = 0.f;

    const unsigned* aPtr = AP + (((size_t)mg * KG) * 32 + lane) * 8;
    const unsigned* bPtr = BP + (((size_t)ngBase * KG) * 32 + lane) * 4;
    const size_t bNg = (size_t)KG * 128;

    for (int kg = 0; kg < KG; kg++) {
        uint4 ah = *(const uint4*)aPtr;
        uint4 al = *(const uint4*)(aPtr + 4);
        aPtr += 256;
#pragma unroll
        for (int j = 0; j < 4; j++) {
            uint4 bb = *(const uint4*)(bPtr + j * bNg);
            mma16816(acc[j], ah.x, ah.y, ah.z, ah.w, bb.x, bb.y);  // hi*hi
            mma16816(acc[j], al.x, al.y, al.z, al.w, bb.x, bb.y);  // lo*hi
            mma16816(acc[j], ah.x, ah.y, ah.z, ah.w, bb.z, bb.w);  // hi*lo
        }
        bPtr += 128;
    }

    const int row = lane >> 2;
    const int col = (lane & 3) * 2;
    const int m0 = mg * 16 + row;
#pragma unroll
    for (int j = 0; j < 4; j++) {
        int n = (ngBase + j) * 8 + col;
        float v00 = acc[j][0], v01 = acc[j][1], v10 = acc[j][2], v11 = acc[j][3];
        if (Add) {
            v00 += Add[(size_t)m0 * ldadd + n];       v01 += Add[(size_t)m0 * ldadd + n + 1];
            v10 += Add[(size_t)(m0 + 8) * ldadd + n]; v11 += Add[(size_t)(m0 + 8) * ldadd + n + 1];
        }
        *(float2*)&C[(size_t)m0 * ldc + n] = make_float2(v00, v01);
        *(float2*)&C[(size_t)(m0 + 8) * ldc + n] = make_float2(v10, v11);
    }
}

// ---------------- persistent encoder: 128 steps of (gates mma + lstm) --------
__global__ __launch_bounds__(256) void k_encoder() {
    const int tid = threadIdx.x, lane = tid & 31, wid = tid >> 5;
    const int wg = blockIdx.x * 8 + wid;        // 0..1023
    const int ng = wg >> 2, mg = wg & 3;
    const unsigned* aBase = g_hP + (((size_t)mg * 32) * 32 + lane) * 8;
    const unsigned* bBase = g_WhhEP + (((size_t)ng * 32) * 32 + lane) * 4;
    const int r = lane >> 2, c2 = (lane & 3) * 2;
    const int m0 = mg * 16 + r;
    const int n = ng * 8 + c2;
    const int lidx = blockIdx.x * 256 + tid;    // 0..32767 = b*512+h
    const int b = lidx >> 9, h = lidx & 511;
    const unsigned nb = gridDim.x;

    for (int t = 0; t < Ss; t++) {
        // gates = h_{t-1} @ Whh_enc^T + Xih[t]
        float acc[4] = {0.f, 0.f, 0.f, 0.f};
        const unsigned* ap = aBase;
        const unsigned* bp = bBase;
#pragma unroll 4
        for (int kg = 0; kg < 32; kg++) {
            uint4 ah = *(const uint4*)ap;
            uint4 al = *(const uint4*)(ap + 4);
            uint4 bb = *(const uint4*)bp;
            mma16816(acc, ah.x, ah.y, ah.z, ah.w, bb.x, bb.y);
            mma16816(acc, al.x, al.y, al.z, al.w, bb.x, bb.y);
            mma16816(acc, ah.x, ah.y, ah.z, ah.w, bb.z, bb.w);
            ap += 256; bp += 128;
        }
        const float* xih = g_Xih + (size_t)t * Bb * G4;
        g_gates[(size_t)m0 * G4 + n]           = acc[0] + xih[(size_t)m0 * G4 + n];
        g_gates[(size_t)m0 * G4 + n + 1]       = acc[1] + xih[(size_t)m0 * G4 + n + 1];
        g_gates[(size_t)(m0 + 8) * G4 + n]     = acc[2] + xih[(size_t)(m0 + 8) * G4 + n];
        g_gates[(size_t)(m0 + 8) * G4 + n + 1] = acc[3] + xih[(size_t)(m0 + 8) * G4 + n + 1];
        gridsync(nb);

        // lstm elementwise (packed-seq semantics)
        const float* gg = g_gates + b * G4;
        float ig = sigf(gg[h]);
        float fg = sigf(gg[Hh + h]);
        float gd = tanhf(gg[2 * Hh + h]);
        float og = sigf(gg[3 * Hh + h]);
        float c_old = g_m[lidx];
        float c_new = fg * c_old + ig * gd;
        float h_new = og * tanhf(c_new);
        bool valid = t < g_lens_s[b];
        float h_old = g_s[lidx];
        float hcur = valid ? h_new : h_old;
        g_m[lidx] = valid ? c_new : c_old;
        g_s[lidx] = hcur;
        g_hs[((size_t)b * Ss + t) * Hh + h] = valid ? h_new : 0.f;
        pack_elem(g_hP, 32, b, h, hcur);
        pack_elem(g_gAP, 64, b, Hh + h, hcur);
        gridsync(nb);
    }
}

// ---------------- decoder LSTM elementwise + packing --------------------------
__global__ void k_lstm_dec() {
    int idx = blockIdx.x * 256 + threadIdx.x;   // over B*H
    int b = idx >> 9, h = idx & (Hh - 1);
    const float* gg = g_gates + b * G4;
    float ig = sigf(gg[h]);
    float fg = sigf(gg[Hh + h]);
    float gd = tanhf(gg[2 * Hh + h]);
    float og = sigf(gg[3 * Hh + h]);
    float c_new = fg * g_m[idx] + ig * gd;
    float h_new = og * tanhf(c_new);
    g_m[idx] = c_new;
    g_s[idx] = h_new;                          // attn reads fp32 s next step
    pack_elem(g_scP, 64, b, h, h_new);         // s_new part of logits A
    pack_elem(g_gAP, 64, b, Hh + h, h_new);    // s part of next gates A
}

// ---------------- att1 = tanh(hs @ W_a1^T) ------------------------------------
__global__ __launch_bounds__(256) void k_att1(const float* __restrict__ Wa1) {
    int w = blockIdx.x * 8 + (threadIdx.x >> 5);   // over B*S warps
    int lane = threadIdx.x & 31;
    int b = w >> 7, s = w & (Ss - 1);
    float acc = 0.f;
    const float* hr = g_hs + ((size_t)b * Ss + s) * Hh;
    for (int k = lane * 4; k < Hh; k += 128) {
        float4 hv = *(const float4*)(hr + k);
        float4 wv = *(const float4*)(Wa1 + k);
        acc += hv.x * wv.x + hv.y * wv.y + hv.z * wv.z + hv.w * wv.w;
    }
#pragma unroll
    for (int off = 16; off; off >>= 1) acc += __shfl_down_sync(0xffffffffu, acc, off);
    if (lane == 0) g_att1[b * Ss + s] = tanhf(acc);
}

// ---------------- attention: scores + softmax over S + context ---------------
__global__ void k_attn(const float* __restrict__ Wa2, const int* __restrict__ mr_len) {
    int b = blockIdx.x;
    int tid = threadIdx.x;   // 128 threads, S = 128
    __shared__ float red[128];
    __shared__ float alphas[128];
    __shared__ float a_sh;

    const float* s = g_s + b * Hh;
    float p = 0.f;
    for (int k = tid; k < Hh; k += 128) p += s[k] * Wa2[k];
    red[tid] = p; __syncthreads();
    for (int off = 64; off; off >>= 1) { if (tid < off) red[tid] += red[tid + off]; __syncthreads(); }
    if (tid == 0) a_sh = tanhf(red[0]);
    __syncthreads();
    float a = a_sh;

    // NOTE: mask uses UNSORTED mr_lengths indexed by the SORTED row (reference bug)
    int len = mr_len[b];
    float e = (tid < len) ? g_att1[b * Ss + tid] * a : -1e9f;

    red[tid] = e; __syncthreads();
    for (int off = 64; off; off >>= 1) { if (tid < off) red[tid] = fmaxf(red[tid], red[tid + off]); __syncthreads(); }
    float mx = red[0]; __syncthreads();
    float ex = expf(e - mx);
    red[tid] = ex; __syncthreads();
    for (int off = 64; off; off >>= 1) { if (tid < off) red[tid] += red[tid + off]; __syncthreads(); }
    alphas[tid] = ex / red[0];
    __syncthreads();

    for (int h = tid; h < Hh; h += 128) {
        float c = 0.f;
        const float* hb = g_hs + (size_t)b * Ss * Hh + h;
#pragma unroll 4
        for (int s2 = 0; s2 < Ss; s2++) c += alphas[s2] * hb[(size_t)s2 * Hh];
        pack_elem(g_gAP, 64, b, h, c);             // ctx part of gates A
        pack_elem(g_scP, 64, b, Hh + h, c);        // ctx part of logits A
    }
}

// ---------------- logits GEMM with smem-staged A + fused softmax partials ----
// Block = 128 N-cols (1 tile), warp = 2 ngs x 4 mgs. A staged in 64KB k-quarters.
__global__ __launch_bounds__(256) void k_logits() {
    extern __shared__ unsigned smA[];   // 64 KB
    const int tid = threadIdx.x;
    const int wid = tid >> 5, lane = tid & 31;
    const int tile = blockIdx.x;               // 0..249
    const int ng0 = tile * 16 + wid * 2;

    float acc[2][4][4];
#pragma unroll
    for (int j = 0; j < 2; j++)
#pragma unroll
        for (int g = 0; g < 4; g++)
#pragma unroll
            for (int i = 0; i < 4; i++) acc[j][g][i] = 0.f;

    for (int q = 0; q < 4; q++) {
        // cooperative load of A quarter: 4096 uint4
#pragma unroll
        for (int i = 0; i < 16; i++) {
            int L = tid + i * 256;
            int p = L & 1;
            int rest = L >> 1;            // (kgl*4+mg)*32 + lane2
            int lane2 = rest & 31;
            int mk = rest >> 5;
            int mg = mk & 3, kgl = mk >> 2;
            const unsigned* src = g_scP + (((size_t)mg * 64 + q * 16 + kgl) * 32 + lane2) * 8 + p * 4;
            *(uint4*)(smA + (size_t)L * 4) = *(const uint4*)src;
        }
        __syncthreads();

        const unsigned* b0 = g_WyP + (((size_t)ng0 * 64 + q * 16) * 32 + lane) * 4;
        const unsigned* b1 = g_WyP + (((size_t)(ng0 + 1) * 64 + q * 16) * 32 + lane) * 4;
        for (int kgl = 0; kgl < 16; kgl++) {
            uint4 bb0 = *(const uint4*)(b0 + kgl * 128);
            uint4 bb1 = *(const uint4*)(b1 + kgl * 128);
#pragma unroll
            for (int mg = 0; mg < 4; mg++) {
                const unsigned* ap = smA + (((kgl * 4 + mg) * 32 + lane) * 8);
                uint4 ah = *(const uint4*)ap;
                uint4 al = *(const uint4*)(ap + 4);
                mma16816(acc[0][mg], ah.x, ah.y, ah.z, ah.w, bb0.x, bb0.y);
                mma16816(acc[0][mg], al.x, al.y, al.z, al.w, bb0.x, bb0.y);
                mma16816(acc[0][mg], ah.x, ah.y, ah.z, ah.w, bb0.z, bb0.w);
                mma16816(acc[1][mg], ah.x, ah.y, ah.z, ah.w, bb1.x, bb1.y);
                mma16816(acc[1][mg], al.x, al.y, al.z, al.w, bb1.x, bb1.y);
                mma16816(acc[1][mg], ah.x, ah.y, ah.z, ah.w, bb1.z, bb1.w);
            }
        }
        __syncthreads();
    }

    // epilogue: write logits, stage tile in smem, reduce row-wise partials
    float* sb = (float*)smA;                    // 64 x 132 floats
    const int r = lane >> 2, c = (lane & 3) * 2;
#pragma unroll
    for (int j = 0; j < 2; j++) {
        int ccol = wid * 16 + j * 8 + c;        // col within tile (0..127)
#pragma unroll
        for (int mg = 0; mg < 4; mg++) {
            int m0 = mg * 16 + r;
            sb[m0 * 132 + ccol] = acc[j][mg][0];
            sb[m0 * 132 + ccol + 1] = acc[j][mg][1];
            sb[(m0 + 8) * 132 + ccol] = acc[j][mg][2];
            sb[(m0 + 8) * 132 + ccol + 1] = acc[j][mg][3];
            size_t g = (size_t)m0 * Vv + tile * 128 + ccol;
            *(float2*)&g_logits[g] = make_float2(acc[j][mg][0], acc[j][mg][1]);
            *(float2*)&g_logits[g + (size_t)8 * Vv] = make_float2(acc[j][mg][2], acc[j][mg][3]);
        }
    }
    __syncthreads();

    int row = tid >> 2, seg = tid & 3;          // 64 rows x 4 segments
    float mx = -1e30f;
#pragma unroll 8
    for (int i = 0; i < 32; i++) mx = fmaxf(mx, sb[row * 132 + seg + i * 4]);
    mx = fmaxf(mx, __shfl_xor_sync(0xffffffffu, mx, 1));
    mx = fmaxf(mx, __shfl_xor_sync(0xffffffffu, mx, 2));
    float sm = 0.f;
#pragma unroll 8
    for (int i = 0; i < 32; i++) sm += __expf(sb[row * 132 + seg + i * 4] - mx);
    sm += __shfl_xor_sync(0xffffffffu, sm, 1);
    sm += __shfl_xor_sync(0xffffffffu, sm, 2);
    if (seg == 0) { g_pmax[tile * 64 + row] = mx; g_psum[tile * 64 + row] = sm; }
}

// ---------------- final softmax + desort scatter ------------------------------
__global__ void k_smfinal(float* __restrict__ out, int t) {
    int b = blockIdx.x >> 3, ch = blockIdx.x & 7;
    int tid = threadIdx.x;   // 256
    __shared__ float red[256];

    float mx = -1e30f;
    for (int i = tid; i < NTILES; i += 256) mx = fmaxf(mx, g_pmax[i * 64 + b]);
    red[tid] = mx; __syncthreads();
    for (int off = 128; off; off >>= 1) { if (tid < off) red[tid] = fmaxf(red[tid], red[tid + off]); __syncthreads(); }
    float gmax = red[0]; __syncthreads();

    float s = 0.f;
    for (int i = tid; i < NTILES; i += 256) s += g_psum[i * 64 + b] * __expf(g_pmax[i * 64 + b] - gmax);
    red[tid] = s; __syncthreads();
    for (int off = 128; off; off >>= 1) { if (tid < off) red[tid] += red[tid + off]; __syncthreads(); }
    float inv = 1.f / red[0];

    const float* lg = g_logits + (size_t)b * Vv + ch * 4000;
    float* dst = out + ((size_t)g_order[b] * Tt + t) * Vv + ch * 4000;
    for (int v = tid; v < 4000; v += 256) dst[v] = __expf(lg[v] - gmax) * inv;
}

// ---------------- launch -------------------------------------------------------
extern "C" void kernel_launch(void* const* d_in, const int* in_sizes, int n_in,
                              void* d_out, int out_size) {
    const int*   mr    = (const int*)d_in[0];
    const int*   ref   = (const int*)d_in[1];
    const int*   lens  = (const int*)d_in[2];
    const float* emb   = (const float*)d_in[3];
    const float* Wih_e = (const float*)d_in[4];
    const float* Whh_e = (const float*)d_in[5];
    const float* Wih_d = (const float*)d_in[6];
    const float* Whh_d = (const float*)d_in[7];
    const float* Wy    = (const float*)d_in[8];
    const float* Ws    = (const float*)d_in[9];
    const float* Wa1   = (const float*)d_in[10];
    const float* Wa2   = (const float*)d_in[11];
    float* out = (float*)d_out;

    float *p_Xih, *p_Gpre, *p_gates, *p_M12;
    unsigned *p_WyP, *p_GcatP, *p_WhhEP, *p_WihEP, *p_WsTP, *p_M1P, *p_WihdA;
    unsigned *p_xP, *p_tgtP, *p_gAP;
    cudaGetSymbolAddress((void**)&p_Xih,    g_Xih);
    cudaGetSymbolAddress((void**)&p_Gpre,   g_Gpre);
    cudaGetSymbolAddress((void**)&p_gates,  g_gates);
    cudaGetSymbolAddress((void**)&p_M12,    g_M12);
    cudaGetSymbolAddress((void**)&p_WyP,    g_WyP);
    cudaGetSymbolAddress((void**)&p_GcatP,  g_GcatP);
    cudaGetSymbolAddress((void**)&p_WhhEP,  g_WhhEP);
    cudaGetSymbolAddress((void**)&p_WihEP,  g_WihEP);
    cudaGetSymbolAddress((void**)&p_WsTP,   g_WsTP);
    cudaGetSymbolAddress((void**)&p_M1P,    g_M1P);
    cudaGetSymbolAddress((void**)&p_WihdA,  g_WihdA);
    cudaGetSymbolAddress((void**)&p_xP,     g_xP);
    cudaGetSymbolAddress((void**)&p_tgtP,   g_tgtP);
    cudaGetSymbolAddress((void**)&p_gAP,    g_gAP);

    cudaFuncSetAttribute(k_logits, cudaFuncAttributeMaxDynamicSharedMemorySize, 65536);

    // ---- prep ----
    k_sort<<<1, 1>>>(lens);
    k_gather_x<<<(Ss * Bb * Ee) / 256, 256>>>(mr, emb);
    k_gather_tgt<<<(Tt * Bb * Ee) / 256, 256>>>(ref, emb);
    k_init<<<128, 256>>>();

    // weight packs
    k_packB<<<32000, 256>>>(Wy, 1024, 1, Wy, 0, 0, 1 << 28, p_WyP, 64);
    k_packB<<<1024, 256>>>(Whh_e, 512, 1, Whh_e, 0, 0, 1 << 28, p_WhhEP, 32);
    k_packB<<<1024, 256>>>(Wih_e, 512, 1, Wih_e, 0, 0, 1 << 28, p_WihEP, 32);
    k_packB<<<512, 256>>>(Ws, 1, 1024, Ws, 0, 0, 1 << 28, p_WsTP, 32);   // Ws^T
    k_packAw<<<4096, 256>>>(Wih_d, p_WihdA, 32);

    // M12 = Wih_d @ Ws  [2048 x 1024]
    mma_gemm<<<dim3(16, 32), 256>>>(p_WihdA, p_WsTP, nullptr, 0, p_M12, KD, 32);
    // pack M1 (cols 0..511) as B for Gpre; [M2|Whh_d] as B for decoder gates
    k_packB<<<1024, 256>>>(p_M12, 1024, 1, p_M12, 0, 0, 1 << 28, p_M1P, 32);
    k_packB<<<2048, 256>>>(p_M12 + 512, 1024, 1, Whh_d, 512, 1, 512, p_GcatP, 64);

    // Xih = x @ W_ih_enc^T  [8192 x 2048]
    mma_gemm<<<dim3(32, 128), 256>>>(p_xP, p_WihEP, nullptr, 0, p_Xih, G4, 32);
    // Gpre = tgt @ M1^T  [3072 x 2048]
    mma_gemm<<<dim3(32, 48), 256>>>(p_tgtP, p_M1P, nullptr, 0, p_Gpre, G4, 32);

    // ---- encoder (persistent) ----
    k_encoder<<<128, 256>>>();

    k_att1<<<(Bb * Ss) / 8, 256>>>(Wa1);

    // ---- decoder ----
    for (int t = 0; t < Tt; t++) {
        k_attn<<<Bb, 128>>>(Wa2, lens);
        mma_gemm<<<dim3(32, 1), 256>>>(p_gAP, p_GcatP,
                                       p_Gpre + (size_t)t * Bb * G4, G4,
                                       p_gates, G4, 64);
        k_lstm_dec<<<(Bb * Hh) / 256, 256>>>();
        k_logits<<<NTILES, 256, 65536>>>();
        k_smfinal<<<Bb * 8, 256>>>(out, t);
    }
}

// round 4
// speedup vs baseline: 2.0396x; 1.1746x over previous
#include <cuda_runtime.h>
#include <cuda_bf16.h>
#include <math.h>

// Problem constants
#define Vv 32000
#define Hh 512
#define Ee 512
#define Bb 64
#define Ss 128
#define Tt 48
#define G4 2048   // 4*H
#define KD 1024   // E+H == 2H
#define NTILES 250   // logits tiles of 128 cols
#define DECB 148     // persistent decoder blocks (<= SM count)

// ---------------- scratch (static device memory; no allocations) -------------
__device__ float g_Xih[Ss * Bb * G4];    // x @ W_ih_enc^T, [s][b][4H]
__device__ float g_Gpre[Tt * Bb * G4];   // tgt @ M1^T (y-part of decoder gates)
__device__ float g_hs[Bb * Ss * Hh];     // encoder hidden states [b][s][h]
__device__ float g_att1[Bb * Ss];        // tanh(hs @ W_a1^T)
__device__ float g_gates[Bb * G4];       // per-step LSTM gates
__device__ float g_logits[Bb * Vv];      // per-step logits
__device__ float g_s[Bb * Hh];           // hidden state fp32 (attn reads)
__device__ float g_m[Bb * Hh];           // cell state
__device__ float g_M12[G4 * KD];         // [M1 | M2] = Wih_d @ Ws  (fp32)
__device__ float g_pmax[NTILES * Bb];
__device__ float g_psum[NTILES * Bb];
__device__ int   g_order[Bb];
__device__ int   g_lens_s[Bb];

// grid barrier
__device__ unsigned g_barcnt = 0;
__device__ volatile unsigned g_bargen = 0;

// ---- packed bf16 split fragment buffers (PLANE-SPLIT layout) ----
// A layout: plane p in {hi,lo}: [p][mg][kg][lane][4] u32; lane stride 16B (coalesced)
// B layout: [ng][kg][lane][4] u32  (hi0,hi1,lo0,lo1 per lane; 16B contiguous)
__device__ unsigned g_WyP [4000u * 64 * 32 * 4];   // Wy    N=32000 K=1024
__device__ unsigned g_GcatP[256u * 64 * 32 * 4];   // [M2|Whh_d] N=2048 K=1024
__device__ unsigned g_WhhEP[256u * 32 * 32 * 4];   // Whh_enc N=2048 K=512
__device__ unsigned g_WihEP[256u * 32 * 32 * 4];   // Wih_enc N=2048 K=512
__device__ unsigned g_WsTP [128u * 32 * 32 * 4];   // Ws^T   N=1024 K=512
__device__ unsigned g_M1P  [256u * 32 * 32 * 4];   // M1     N=2048 K=512
__device__ unsigned g_WihdA[128u * 32 * 32 * 8];   // Wih_d A-layout M=2048 K=512
__device__ unsigned g_xP  [512u * 32 * 32 * 8];    // x    M=8192 K=512
__device__ unsigned g_tgtP[192u * 32 * 32 * 8];    // tgt  M=3072 K=512
__device__ unsigned g_hP  [  4u * 32 * 32 * 8];    // enc h M=64 K=512
__device__ unsigned g_gAP [  4u * 64 * 32 * 8];    // [ctx|s] M=64 K=1024 (gates A)
__device__ unsigned g_scP [  4u * 64 * 32 * 8];    // [s_new|ctx] M=64 K=1024 (logits A)

// plane offsets (in u32 words) = half of each A buffer
#define PO_WIHD ((size_t)128u * 32 * 32 * 4)
#define PO_X    ((size_t)512u * 32 * 32 * 4)
#define PO_TGT  ((size_t)192u * 32 * 32 * 4)
#define PO_H    ((size_t)4u * 32 * 32 * 4)
#define PO_GA   ((size_t)4u * 64 * 32 * 4)
#define PO_SC   ((size_t)4u * 64 * 32 * 4)

// ---------------- helpers ----------------------------------------------------
__device__ __forceinline__ float sigf(float x) { return 1.f / (1.f + expf(-x)); }

__device__ __forceinline__ unsigned short f2bf(float v) {
    __nv_bfloat16 h = __float2bfloat16(v);
    return __bfloat16_as_ushort(h);
}

// write one fp32 element (m,k) into plane-split A fragment layout
__device__ __forceinline__ void pack_elem(unsigned* dst, int KG, size_t po, int m, int k, float v) {
    int mg = m >> 4, ri = m & 15, kg = k >> 4, c = k & 15;
    int lane = ((ri & 7) << 2) + ((c & 7) >> 1);
    int reg  = (ri >> 3) + ((c >> 3) << 1);
    size_t base = (((size_t)mg * KG + kg) * 32 + lane) * 4 + reg;
    unsigned short hb = f2bf(v);
    float r = v - __bfloat162float(__ushort_as_bfloat16(hb));
    unsigned short lb = f2bf(r);
    ((unsigned short*)(dst + base))[c & 1] = hb;
    ((unsigned short*)(dst + po + base))[c & 1] = lb;
}

__device__ __forceinline__ void mma16816(float* c,
    unsigned a0, unsigned a1, unsigned a2, unsigned a3,
    unsigned b0, unsigned b1)
{
    asm volatile(
        "mma.sync.aligned.m16n8k16.row.col.f32.bf16.bf16.f32 "
        "{%0,%1,%2,%3}, {%4,%5,%6,%7}, {%8,%9}, {%0,%1,%2,%3};"
        : "+f"(c[0]), "+f"(c[1]), "+f"(c[2]), "+f"(c[3])
        : "r"(a0), "r"(a1), "r"(a2), "r"(a3), "r"(b0), "r"(b1));
}

__device__ __forceinline__ void gridsync(unsigned nb) {
    __threadfence();
    __syncthreads();
    if (threadIdx.x == 0) {
        unsigned gen = g_bargen;
        if (atomicAdd(&g_barcnt, 1u) == nb - 1u) {
            g_barcnt = 0;
            __threadfence();
            g_bargen = gen + 1u;
        } else {
            while (g_bargen == gen) { }
        }
    }
    __syncthreads();
    __threadfence();
}

// ---------------- sort: stable argsort of -lengths ---------------------------
__global__ void k_sort(const int* __restrict__ lens) {
    int idx[Bb];
    for (int i = 0; i < Bb; i++) idx[i] = i;
    for (int i = 1; i < Bb; i++) {
        int v = idx[i];
        int kv = lens[v];
        int j = i - 1;
        while (j >= 0 && lens[idx[j]] < kv) { idx[j + 1] = idx[j]; j--; }
        idx[j + 1] = v;
    }
    for (int i = 0; i < Bb; i++) {
        g_order[i] = idx[i];
        g_lens_s[i] = lens[idx[i]];
    }
}

// ---------------- gathers (write directly into packed A layout) --------------
__global__ void k_gather_x(const int* __restrict__ mr, const float* __restrict__ emb) {
    int idx = blockIdx.x * 256 + threadIdx.x;           // over S*B*E
    int e = idx & (Ee - 1);
    int b = (idx >> 9) & (Bb - 1);
    int s = idx >> 15;
    int tok = mr[g_order[b] * Ss + s];
    float v = emb[(size_t)tok * Ee + e];
    pack_elem(g_xP, 32, PO_X, s * Bb + b, e, v);
}

__global__ void k_gather_tgt(const int* __restrict__ ref, const float* __restrict__ emb) {
    int idx = blockIdx.x * 256 + threadIdx.x;           // over T*B*E
    int e = idx & (Ee - 1);
    int b = (idx >> 9) & (Bb - 1);
    int t = idx >> 15;
    int tok = ref[g_order[b] * Tt + t];
    float v = emb[(size_t)tok * Ee + e];
    pack_elem(g_tgtP, 32, PO_TGT, t * Bb + b, e, v);
}

__global__ void k_init() {
    int idx = blockIdx.x * 256 + threadIdx.x;   // 32768 threads
    g_s[idx] = 0.f;
    g_m[idx] = 0.f;
    g_hP[idx] = 0u;
}

// ---------------- pack A weight (row-major fp32 -> A frag) -------------------
__global__ void k_packAw(const float* __restrict__ src, unsigned* __restrict__ dst,
                         int KG, size_t po) {
    int idx = blockIdx.x * 256 + threadIdx.x;
    int K = KG * 16;
    int m = idx / K, k = idx - m * K;
    pack_elem(dst, KG, po, m, k, src[idx]);
}

// ---------------- pack B matrices into fragment layout (general strides) -----
__global__ void k_packB(const float* __restrict__ s1, long sN1, long sK1,
                        const float* __restrict__ s2, long sN2, long sK2,
                        int ksplit, unsigned* __restrict__ dst, int KG)
{
    int idx = blockIdx.x * 256 + threadIdx.x;  // (ng*KG + kg)*32 + lane
    int lane = idx & 31;
    int kg = (idx >> 5) % KG;
    int ng = idx / (32 * KG);
    int n = ng * 8 + (lane >> 2);
    int k0 = kg * 16 + (lane & 3) * 2;
    float e[4];
    int ks[4] = { k0, k0 + 1, k0 + 8, k0 + 9 };
#pragma unroll
    for (int i = 0; i < 4; i++) {
        int k = ks[i];
        e[i] = (k >= ksplit) ? s2[(size_t)n * sN2 + (size_t)(k - ksplit) * sK2]
                             : s1[(size_t)n * sN1 + (size_t)k * sK1];
    }
    unsigned short hb[4], lb[4];
#pragma unroll
    for (int i = 0; i < 4; i++) {
        hb[i] = f2bf(e[i]);
        lb[i] = f2bf(e[i] - __bfloat162float(__ushort_as_bfloat16(hb[i])));
    }
    uint4 w;
    w.x = (unsigned)hb[0] | ((unsigned)hb[1] << 16);
    w.y = (unsigned)hb[2] | ((unsigned)hb[3] << 16);
    w.z = (unsigned)lb[0] | ((unsigned)lb[1] << 16);
    w.w = (unsigned)lb[2] | ((unsigned)lb[3] << 16);
    *(uint4*)(dst + (size_t)idx * 4) = w;
}

// ---------------- generic split-bf16 tensor-core GEMM (prep only) ------------
__global__ __launch_bounds__(256) void mma_gemm(
    const unsigned* __restrict__ AP, size_t poA,
    const unsigned* __restrict__ BP,
    const float* __restrict__ Add, int ldadd,
    float* __restrict__ C, int ldc, int KG)
{
    const int lane = threadIdx.x & 31;
    const int w = threadIdx.x >> 5;
    const int mg = blockIdx.y * 4 + (w & 3);
    const int ngBase = blockIdx.x * 8 + (w >> 2) * 4;

    float acc[4][4];
#pragma unroll
    for (int j = 0; j < 4; j++)
#pragma unroll
        for (int i = 0; i < 4; i++) acc[j][i] = 0.f;

    const unsigned* aPtr = AP + (((size_t)mg * KG) * 32 + lane) * 4;
    const unsigned* bPtr = BP + (((size_t)ngBase * KG) * 32 + lane) * 4;
    const size_t bNg = (size_t)KG * 128;

    for (int kg = 0; kg < KG; kg++) {
        uint4 ah = *(const uint4*)aPtr;
        uint4 al = *(const uint4*)(aPtr + poA);
        aPtr += 128;
#pragma unroll
        for (int j = 0; j < 4; j++) {
            uint4 bb = *(const uint4*)(bPtr + j * bNg);
            mma16816(acc[j], ah.x, ah.y, ah.z, ah.w, bb.x, bb.y);
            mma16816(acc[j], al.x, al.y, al.z, al.w, bb.x, bb.y);
            mma16816(acc[j], ah.x, ah.y, ah.z, ah.w, bb.z, bb.w);
        }
        bPtr += 128;
    }

    const int row = lane >> 2;
    const int col = (lane & 3) * 2;
    const int m0 = mg * 16 + row;
#pragma unroll
    for (int j = 0; j < 4; j++) {
        int n = (ngBase + j) * 8 + col;
        float v00 = acc[j][0], v01 = acc[j][1], v10 = acc[j][2], v11 = acc[j][3];
        if (Add) {
            v00 += Add[(size_t)m0 * ldadd + n];       v01 += Add[(size_t)m0 * ldadd + n + 1];
            v10 += Add[(size_t)(m0 + 8) * ldadd + n]; v11 += Add[(size_t)(m0 + 8) * ldadd + n + 1];
        }
        *(float2*)&C[(size_t)m0 * ldc + n] = make_float2(v00, v01);
        *(float2*)&C[(size_t)(m0 + 8) * ldc + n] = make_float2(v10, v11);
    }
}

// ---------------- persistent encoder: 128 steps of (gates mma + lstm) --------
__global__ __launch_bounds__(256) void k_encoder() {
    const int tid = threadIdx.x, lane = tid & 31, wid = tid >> 5;
    const int wg = blockIdx.x * 8 + wid;        // 0..1023
    const int ng = wg >> 2, mg = wg & 3;
    const unsigned* aBase = g_hP + (((size_t)mg * 32) * 32 + lane) * 4;
    const unsigned* bBase = g_WhhEP + (((size_t)ng * 32) * 32 + lane) * 4;
    const int r = lane >> 2, c2 = (lane & 3) * 2;
    const int m0 = mg * 16 + r;
    const int n = ng * 8 + c2;
    const int lidx = blockIdx.x * 256 + tid;    // 0..32767 = b*512+h
    const int b = lidx >> 9, h = lidx & 511;
    const unsigned nb = gridDim.x;

    for (int t = 0; t < Ss; t++) {
        float acc[4] = {0.f, 0.f, 0.f, 0.f};
        const unsigned* ap = aBase;
        const unsigned* bp = bBase;
#pragma unroll 4
        for (int kg = 0; kg < 32; kg++) {
            uint4 ah = *(const uint4*)ap;
            uint4 al = *(const uint4*)(ap + PO_H);
            uint4 bb = *(const uint4*)bp;
            mma16816(acc, ah.x, ah.y, ah.z, ah.w, bb.x, bb.y);
            mma16816(acc, al.x, al.y, al.z, al.w, bb.x, bb.y);
            mma16816(acc, ah.x, ah.y, ah.z, ah.w, bb.z, bb.w);
            ap += 128; bp += 128;
        }
        const float* xih = g_Xih + (size_t)t * Bb * G4;
        g_gates[(size_t)m0 * G4 + n]           = acc[0] + xih[(size_t)m0 * G4 + n];
        g_gates[(size_t)m0 * G4 + n + 1]       = acc[1] + xih[(size_t)m0 * G4 + n + 1];
        g_gates[(size_t)(m0 + 8) * G4 + n]     = acc[2] + xih[(size_t)(m0 + 8) * G4 + n];
        g_gates[(size_t)(m0 + 8) * G4 + n + 1] = acc[3] + xih[(size_t)(m0 + 8) * G4 + n + 1];
        gridsync(nb);

        const float* gg = g_gates + b * G4;
        float ig = sigf(gg[h]);
        float fg = sigf(gg[Hh + h]);
        float gd = tanhf(gg[2 * Hh + h]);
        float og = sigf(gg[3 * Hh + h]);
        float c_old = g_m[lidx];
        float c_new = fg * c_old + ig * gd;
        float h_new = og * tanhf(c_new);
        bool valid = t < g_lens_s[b];
        float h_old = g_s[lidx];
        float hcur = valid ? h_new : h_old;
        g_m[lidx] = valid ? c_new : c_old;
        g_s[lidx] = hcur;
        g_hs[((size_t)b * Ss + t) * Hh + h] = valid ? h_new : 0.f;
        pack_elem(g_hP, 32, PO_H, b, h, hcur);
        pack_elem(g_gAP, 64, PO_GA, b, Hh + h, hcur);
        gridsync(nb);
    }
}

// ---------------- att1 = tanh(hs @ W_a1^T) ------------------------------------
__global__ __launch_bounds__(256) void k_att1(const float* __restrict__ Wa1) {
    int w = blockIdx.x * 8 + (threadIdx.x >> 5);   // over B*S warps
    int lane = threadIdx.x & 31;
    int b = w >> 7, s = w & (Ss - 1);
    float acc = 0.f;
    const float* hr = g_hs + ((size_t)b * Ss + s) * Hh;
    for (int k = lane * 4; k < Hh; k += 128) {
        float4 hv = *(const float4*)(hr + k);
        float4 wv = *(const float4*)(Wa1 + k);
        acc += hv.x * wv.x + hv.y * wv.y + hv.z * wv.z + hv.w * wv.w;
    }
#pragma unroll
    for (int off = 16; off; off >>= 1) acc += __shfl_down_sync(0xffffffffu, acc, off);
    if (lane == 0) g_att1[b * Ss + s] = tanhf(acc);
}

// ---------------- final softmax + desort scatter (device body) ---------------
__device__ void smfinal_body(int b, int t, float* __restrict__ out,
                             float* s_red, int tid) {
    float mx = -1e30f;
    for (int i = tid; i < NTILES; i += 256) mx = fmaxf(mx, g_pmax[i * 64 + b]);
    s_red[tid] = mx; __syncthreads();
    for (int off = 128; off; off >>= 1) { if (tid < off) s_red[tid] = fmaxf(s_red[tid], s_red[tid + off]); __syncthreads(); }
    float gmax = s_red[0]; __syncthreads();
    float s = 0.f;
    for (int i = tid; i < NTILES; i += 256) s += g_psum[i * 64 + b] * __expf(g_pmax[i * 64 + b] - gmax);
    s_red[tid] = s; __syncthreads();
    for (int off = 128; off; off >>= 1) { if (tid < off) s_red[tid] += s_red[tid + off]; __syncthreads(); }
    float inv = 1.f / s_red[0];
    __syncthreads();
    const float* lg = g_logits + (size_t)b * Vv;
    float* dst = out + ((size_t)g_order[b] * Tt + t) * Vv;
    for (int v = tid; v < Vv; v += 256) dst[v] = __expf(lg[v] - gmax) * inv;
}

// ---------------- persistent fused decoder ------------------------------------
__global__ __launch_bounds__(256) void k_decoder(const float* __restrict__ Wa2,
                                                 const int* __restrict__ mr_len,
                                                 float* __restrict__ out) {
    extern __shared__ unsigned smA[];          // 128 KB A stage / epilogue buffer
    __shared__ float s_red[256];
    __shared__ float s_alph[Ss];
    __shared__ float s_a;
    const int tid = threadIdx.x, lane = tid & 31, wid = tid >> 5;
    const int bid = blockIdx.x;
    const unsigned nb = gridDim.x;

    for (int t = 0; t < Tt; t++) {
        // ---------- P0: attn (bid<64) || smfinal(t-1) (64<=bid<128) ----------
        if (bid < Bb) {
            const int b = bid;
            const float* sv = g_s + b * Hh;
            float p = 0.f;
            for (int k = tid; k < Hh; k += 256) p += sv[k] * Wa2[k];
            s_red[tid] = p; __syncthreads();
            for (int off = 128; off; off >>= 1) { if (tid < off) s_red[tid] += s_red[tid + off]; __syncthreads(); }
            if (tid == 0) s_a = tanhf(s_red[0]);
            __syncthreads();
            float a = s_a;
            float e = -1e30f;
            if (tid < Ss) {
                // reference bug preserved: UNSORTED lengths index sorted row
                int len = mr_len[b];
                e = (tid < len) ? g_att1[b * Ss + tid] * a : -1e9f;
            }
            s_red[tid] = e; __syncthreads();
            for (int off = 128; off; off >>= 1) { if (tid < off) s_red[tid] = fmaxf(s_red[tid], s_red[tid + off]); __syncthreads(); }
            float mx = s_red[0]; __syncthreads();
            float ex = (tid < Ss) ? __expf(e - mx) : 0.f;
            s_red[tid] = ex; __syncthreads();
            for (int off = 128; off; off >>= 1) { if (tid < off) s_red[tid] += s_red[tid + off]; __syncthreads(); }
            if (tid < Ss) s_alph[tid] = ex / s_red[0];
            __syncthreads();
            // ctx: coalesced — thread owns float2 at h = 2*tid
            float cx = 0.f, cy = 0.f;
            const float2* hb = (const float2*)(g_hs + (size_t)b * Ss * Hh) + tid;
#pragma unroll 8
            for (int s2 = 0; s2 < Ss; s2++) {
                float av = s_alph[s2];
                float2 hv = hb[(size_t)s2 * (Hh / 2)];
                cx = fmaf(av, hv.x, cx);
                cy = fmaf(av, hv.y, cy);
            }
            int h0 = tid * 2;
            pack_elem(g_gAP, 64, PO_GA, b, h0, cx);
            pack_elem(g_gAP, 64, PO_GA, b, h0 + 1, cy);
            pack_elem(g_scP, 64, PO_SC, b, Hh + h0, cx);
            pack_elem(g_scP, 64, PO_SC, b, Hh + h0 + 1, cy);
        } else if (t > 0 && bid - Bb < Bb) {
            smfinal_body(bid - Bb, t - 1, out, s_red, tid);
        }
        gridsync(nb);

        // ---------- P1: gates = [ctx|s] @ [M2|Whh_d]^T + Gpre[t] ----------
        {
            int w = bid * 8 + wid;
            if (w < 1024) {
                int mg = w & 3, ng = w >> 2;
                float acc[4] = {0.f, 0.f, 0.f, 0.f};
                const unsigned* ap = g_gAP + (((size_t)mg * 64) * 32 + lane) * 4;
                const unsigned* bp = g_GcatP + (((size_t)ng * 64) * 32 + lane) * 4;
#pragma unroll 4
                for (int kg = 0; kg < 64; kg++) {
                    uint4 ah = *(const uint4*)ap;
                    uint4 al = *(const uint4*)(ap + PO_GA);
                    uint4 bb = *(const uint4*)bp;
                    mma16816(acc, ah.x, ah.y, ah.z, ah.w, bb.x, bb.y);
                    mma16816(acc, al.x, al.y, al.z, al.w, bb.x, bb.y);
                    mma16816(acc, ah.x, ah.y, ah.z, ah.w, bb.z, bb.w);
                    ap += 128; bp += 128;
                }
                int r = lane >> 2, cc = (lane & 3) * 2;
                int m0 = mg * 16 + r, n = ng * 8 + cc;
                const float* adp = g_Gpre + (size_t)t * Bb * G4;
                g_gates[(size_t)m0 * G4 + n]           = acc[0] + adp[(size_t)m0 * G4 + n];
                g_gates[(size_t)m0 * G4 + n + 1]       = acc[1] + adp[(size_t)m0 * G4 + n + 1];
                g_gates[(size_t)(m0 + 8) * G4 + n]     = acc[2] + adp[(size_t)(m0 + 8) * G4 + n];
                g_gates[(size_t)(m0 + 8) * G4 + n + 1] = acc[3] + adp[(size_t)(m0 + 8) * G4 + n + 1];
            }
        }
        gridsync(nb);

        // ---------- P2: lstm elementwise + pack ----------
        if (bid < 128) {
            int idx = bid * 256 + tid;
            int b = idx >> 9, h = idx & 511;
            const float* gg = g_gates + b * G4;
            float ig = sigf(gg[h]);
            float fg = sigf(gg[Hh + h]);
            float gd = tanhf(gg[2 * Hh + h]);
            float og = sigf(gg[3 * Hh + h]);
            float c_new = fg * g_m[idx] + ig * gd;
            float h_new = og * tanhf(c_new);
            g_m[idx] = c_new;
            g_s[idx] = h_new;
            pack_elem(g_scP, 64, PO_SC, b, h, h_new);
            pack_elem(g_gAP, 64, PO_GA, b, Hh + h, h_new);
        }
        gridsync(nb);

        // ---------- P3: logits tiles + partial softmax ----------
        {
            const int tile0 = bid;
            const int tile1 = bid + DECB;
            float acc[2][2][4][4];
#pragma unroll
            for (int ts = 0; ts < 2; ts++)
#pragma unroll
                for (int j = 0; j < 2; j++)
#pragma unroll
                    for (int g = 0; g < 4; g++)
#pragma unroll
                        for (int i = 0; i < 4; i++) acc[ts][j][g][i] = 0.f;

            for (int q = 0; q < 2; q++) {
                // stage A half-q: 8192 uint4, conflict-free dst, coalesced src
#pragma unroll
                for (int i = 0; i < 32; i++) {
                    int L = tid + i * 256;
                    int l2 = L & 31, pp = (L >> 5) & 1, mg = (L >> 6) & 3, kgl = L >> 8;
                    const unsigned* src = g_scP + (size_t)pp * PO_SC
                        + (((size_t)mg * 64 + q * 32 + kgl) * 32 + l2) * 4;
                    *(uint4*)(smA + (size_t)L * 4) = *(const uint4*)src;
                }
                __syncthreads();

                const int ng00 = tile0 * 16 + wid * 2;
                const int ng10 = tile1 * 16 + wid * 2;
                const unsigned* b00 = g_WyP + (((size_t)ng00 * 64 + q * 32) * 32 + lane) * 4;
                const unsigned* b01 = g_WyP + (((size_t)(ng00 + 1) * 64 + q * 32) * 32 + lane) * 4;
                const unsigned* b10 = g_WyP + (((size_t)ng10 * 64 + q * 32) * 32 + lane) * 4;
                const unsigned* b11 = g_WyP + (((size_t)(ng10 + 1) * 64 + q * 32) * 32 + lane) * 4;

                for (int kgl = 0; kgl < 32; kgl++) {
                    uint4 ah[4], al[4];
#pragma unroll
                    for (int mg = 0; mg < 4; mg++) {
                        const unsigned* ap = smA + (((size_t)(kgl * 4 + mg) * 2) * 32 + lane) * 4;
                        ah[mg] = *(const uint4*)ap;
                        al[mg] = *(const uint4*)(ap + 128);
                    }
                    {
                        uint4 bb0 = *(const uint4*)(b00 + kgl * 128);
                        uint4 bb1 = *(const uint4*)(b01 + kgl * 128);
#pragma unroll
                        for (int mg = 0; mg < 4; mg++) {
                            mma16816(acc[0][0][mg], ah[mg].x, ah[mg].y, ah[mg].z, ah[mg].w, bb0.x, bb0.y);
                            mma16816(acc[0][0][mg], al[mg].x, al[mg].y, al[mg].z, al[mg].w, bb0.x, bb0.y);
                            mma16816(acc[0][0][mg], ah[mg].x, ah[mg].y, ah[mg].z, ah[mg].w, bb0.z, bb0.w);
                            mma16816(acc[0][1][mg], ah[mg].x, ah[mg].y, ah[mg].z, ah[mg].w, bb1.x, bb1.y);
                            mma16816(acc[0][1][mg], al[mg].x, al[mg].y, al[mg].z, al[mg].w, bb1.x, bb1.y);
                            mma16816(acc[0][1][mg], ah[mg].x, ah[mg].y, ah[mg].z, ah[mg].w, bb1.z, bb1.w);
                        }
                    }
                    if (tile1 < NTILES) {
                        uint4 bb0 = *(const uint4*)(b10 + kgl * 128);
                        uint4 bb1 = *(const uint4*)(b11 + kgl * 128);
#pragma unroll
                        for (int mg = 0; mg < 4; mg++) {
                            mma16816(acc[1][0][mg], ah[mg].x, ah[mg].y, ah[mg].z, ah[mg].w, bb0.x, bb0.y);
                            mma16816(acc[1][0][mg], al[mg].x, al[mg].y, al[mg].z, al[mg].w, bb0.x, bb0.y);
                            mma16816(acc[1][0][mg], ah[mg].x, ah[mg].y, ah[mg].z, ah[mg].w, bb0.z, bb0.w);
                            mma16816(acc[1][1][mg], ah[mg].x, ah[mg].y, ah[mg].z, ah[mg].w, bb1.x, bb1.y);
                            mma16816(acc[1][1][mg], al[mg].x, al[mg].y, al[mg].z, al[mg].w, bb1.x, bb1.y);
                            mma16816(acc[1][1][mg], ah[mg].x, ah[mg].y, ah[mg].z, ah[mg].w, bb1.z, bb1.w);
                        }
                    }
                }
                __syncthreads();
            }

            // epilogue per tile: write logits + row partials
            float* sb = (float*)smA;
            const int r = lane >> 2, c = (lane & 3) * 2;
#pragma unroll
            for (int ts = 0; ts < 2; ts++) {
                int tile = ts ? tile1 : tile0;
                if (tile >= NTILES) break;
                __syncthreads();
#pragma unroll
                for (int j = 0; j < 2; j++) {
                    int ccol = wid * 16 + j * 8 + c;
#pragma unroll
                    for (int mg = 0; mg < 4; mg++) {
                        int m0 = mg * 16 + r;
                        float v0 = acc[ts][j][mg][0], v1 = acc[ts][j][mg][1];
                        float v2 = acc[ts][j][mg][2], v3 = acc[ts][j][mg][3];
                        sb[m0 * 132 + ccol] = v0;       sb[m0 * 132 + ccol + 1] = v1;
                        sb[(m0 + 8) * 132 + ccol] = v2; sb[(m0 + 8) * 132 + ccol + 1] = v3;
                        size_t g = (size_t)m0 * Vv + (size_t)tile * 128 + ccol;
                        *(float2*)&g_logits[g] = make_float2(v0, v1);
                        *(float2*)&g_logits[g + (size_t)8 * Vv] = make_float2(v2, v3);
                    }
                }
                __syncthreads();
                int row = tid >> 2, seg = tid & 3;
                float mx2 = -1e30f;
#pragma unroll 8
                for (int i = 0; i < 32; i++) mx2 = fmaxf(mx2, sb[row * 132 + seg + i * 4]);
                mx2 = fmaxf(mx2, __shfl_xor_sync(0xffffffffu, mx2, 1));
                mx2 = fmaxf(mx2, __shfl_xor_sync(0xffffffffu, mx2, 2));
                float sm = 0.f;
#pragma unroll 8
                for (int i = 0; i < 32; i++) sm += __expf(sb[row * 132 + seg + i * 4] - mx2);
                sm += __shfl_xor_sync(0xffffffffu, sm, 1);
                sm += __shfl_xor_sync(0xffffffffu, sm, 2);
                if (seg == 0) { g_pmax[tile * 64 + row] = mx2; g_psum[tile * 64 + row] = sm; }
            }
        }
        gridsync(nb);
    }

    // final scatter for t = Tt-1
    if (bid >= Bb && bid - Bb < Bb) smfinal_body(bid - Bb, Tt - 1, out, s_red, tid);
}

// ---------------- launch -------------------------------------------------------
extern "C" void kernel_launch(void* const* d_in, const int* in_sizes, int n_in,
                              void* d_out, int out_size) {
    const int*   mr    = (const int*)d_in[0];
    const int*   ref   = (const int*)d_in[1];
    const int*   lens  = (const int*)d_in[2];
    const float* emb   = (const float*)d_in[3];
    const float* Wih_e = (const float*)d_in[4];
    const float* Whh_e = (const float*)d_in[5];
    const float* Wih_d = (const float*)d_in[6];
    const float* Whh_d = (const float*)d_in[7];
    const float* Wy    = (const float*)d_in[8];
    const float* Ws    = (const float*)d_in[9];
    const float* Wa1   = (const float*)d_in[10];
    const float* Wa2   = (const float*)d_in[11];
    float* out = (float*)d_out;

    float *p_Xih, *p_Gpre, *p_M12;
    unsigned *p_WyP, *p_GcatP, *p_WhhEP, *p_WihEP, *p_WsTP, *p_M1P, *p_WihdA;
    unsigned *p_xP, *p_tgtP;
    cudaGetSymbolAddress((void**)&p_Xih,    g_Xih);
    cudaGetSymbolAddress((void**)&p_Gpre,   g_Gpre);
    cudaGetSymbolAddress((void**)&p_M12,    g_M12);
    cudaGetSymbolAddress((void**)&p_WyP,    g_WyP);
    cudaGetSymbolAddress((void**)&p_GcatP,  g_GcatP);
    cudaGetSymbolAddress((void**)&p_WhhEP,  g_WhhEP);
    cudaGetSymbolAddress((void**)&p_WihEP,  g_WihEP);
    cudaGetSymbolAddress((void**)&p_WsTP,   g_WsTP);
    cudaGetSymbolAddress((void**)&p_M1P,    g_M1P);
    cudaGetSymbolAddress((void**)&p_WihdA,  g_WihdA);
    cudaGetSymbolAddress((void**)&p_xP,     g_xP);
    cudaGetSymbolAddress((void**)&p_tgtP,   g_tgtP);

    cudaFuncSetAttribute(k_decoder, cudaFuncAttributeMaxDynamicSharedMemorySize, 131072);

    // ---- prep ----
    k_sort<<<1, 1>>>(lens);
    k_gather_x<<<(Ss * Bb * Ee) / 256, 256>>>(mr, emb);
    k_gather_tgt<<<(Tt * Bb * Ee) / 256, 256>>>(ref, emb);
    k_init<<<128, 256>>>();

    // weight packs
    k_packB<<<32000, 256>>>(Wy, 1024, 1, Wy, 0, 0, 1 << 28, p_WyP, 64);
    k_packB<<<1024, 256>>>(Whh_e, 512, 1, Whh_e, 0, 0, 1 << 28, p_WhhEP, 32);
    k_packB<<<1024, 256>>>(Wih_e, 512, 1, Wih_e, 0, 0, 1 << 28, p_WihEP, 32);
    k_packB<<<512, 256>>>(Ws, 1, 1024, Ws, 0, 0, 1 << 28, p_WsTP, 32);   // Ws^T
    k_packAw<<<4096, 256>>>(Wih_d, p_WihdA, 32, PO_WIHD);

    // M12 = Wih_d @ Ws  [2048 x 1024]
    mma_gemm<<<dim3(16, 32), 256>>>(p_WihdA, PO_WIHD, p_WsTP, nullptr, 0, p_M12, KD, 32);
    k_packB<<<1024, 256>>>(p_M12, 1024, 1, p_M12, 0, 0, 1 << 28, p_M1P, 32);
    k_packB<<<2048, 256>>>(p_M12 + 512, 1024, 1, Whh_d, 512, 1, 512, p_GcatP, 64);

    // Xih = x @ W_ih_enc^T  [8192 x 2048]
    mma_gemm<<<dim3(32, 128), 256>>>(p_xP, PO_X, p_WihEP, nullptr, 0, p_Xih, G4, 32);
    // Gpre = tgt @ M1^T  [3072 x 2048]
    mma_gemm<<<dim3(32, 48), 256>>>(p_tgtP, PO_TGT, p_M1P, nullptr, 0, p_Gpre, G4, 32);

    // ---- encoder (persistent) ----
    k_encoder<<<128, 256>>>();

    k_att1<<<(Bb * Ss) / 8, 256>>>(Wa1);

    // ---- decoder (single persistent kernel) ----
    k_decoder<<<DECB, 256, 131072>>>(Wa2, lens, out);
}

// round 5
// speedup vs baseline: 2.5849x; 1.2673x over previous
#include <cuda_runtime.h>
#include <cuda_bf16.h>
#include <math.h>

// Problem constants
#define Vv 32000
#define Hh 512
#define Ee 512
#define Bb 64
#define Ss 128
#define Tt 48
#define G4 2048   // 4*H
#define KD 1024   // E+H == 2H
#define NTILES 250   // logits tiles of 128 cols
#define DECB 148     // persistent decoder blocks (<= SM count)

// ---------------- scratch (static device memory; no allocations) -------------
__device__ float g_Xih[Ss * Bb * G4];    // x @ W_ih_enc^T, [s][b][4H]
__device__ float g_Gpre[Tt * Bb * G4];   // tgt @ M1^T (y-part of decoder gates)
__device__ float g_hs[Bb * Ss * Hh];     // encoder hidden states [b][s][h]
__device__ float g_att1[Bb * Ss];        // tanh(hs @ W_a1^T)
__device__ float g_gates[Bb * G4];       // per-step LSTM gates
__device__ float g_logits[Bb * Vv];      // per-step logits
__device__ float g_s[Bb * Hh];           // hidden state fp32 (attn reads)
__device__ float g_m[Bb * Hh];           // cell state
__device__ float g_M12[G4 * KD];         // [M1 | M2] = Wih_d @ Ws  (fp32)
__device__ float g_pmax[NTILES * Bb];
__device__ float g_psum[NTILES * Bb];
__device__ int   g_order[Bb];
__device__ int   g_lens_s[Bb];

// grid barrier
__device__ unsigned g_barcnt = 0;
__device__ volatile unsigned g_bargen = 0;

// ---- packed bf16 split fragment buffers (PLANE-SPLIT layout) ----
// A layout: plane p in {hi,lo}: [p][mg][kg][lane][4] u32; lane stride 16B (coalesced)
// B layout: [ng][kg][lane][4] u32  (hi0,hi1,lo0,lo1 per lane; 16B contiguous)
__device__ unsigned g_WyP [4000u * 64 * 32 * 4];   // Wy    N=32000 K=1024
__device__ unsigned g_GcatP[256u * 64 * 32 * 4];   // [M2|Whh_d] N=2048 K=1024
__device__ unsigned g_WhhEP[256u * 32 * 32 * 4];   // Whh_enc N=2048 K=512
__device__ unsigned g_WihEP[256u * 32 * 32 * 4];   // Wih_enc N=2048 K=512
__device__ unsigned g_WsTP [128u * 32 * 32 * 4];   // Ws^T   N=1024 K=512
__device__ unsigned g_M1P  [256u * 32 * 32 * 4];   // M1     N=2048 K=512
__device__ unsigned g_WihdA[128u * 32 * 32 * 8];   // Wih_d A-layout M=2048 K=512
__device__ unsigned g_xP  [512u * 32 * 32 * 8];    // x    M=8192 K=512
__device__ unsigned g_tgtP[192u * 32 * 32 * 8];    // tgt  M=3072 K=512
__device__ unsigned g_hP  [  4u * 32 * 32 * 8];    // enc h M=64 K=512
__device__ unsigned g_gAP [  4u * 64 * 32 * 8];    // [ctx|s] M=64 K=1024 (gates A)
__device__ unsigned g_scP [  4u * 64 * 32 * 8];    // [s_new|ctx] M=64 K=1024 (logits A)

// plane offsets (in u32 words) = half of each A buffer
#define PO_WIHD ((size_t)128u * 32 * 32 * 4)
#define PO_X    ((size_t)512u * 32 * 32 * 4)
#define PO_TGT  ((size_t)192u * 32 * 32 * 4)
#define PO_H    ((size_t)4u * 32 * 32 * 4)
#define PO_GA   ((size_t)4u * 64 * 32 * 4)
#define PO_SC   ((size_t)4u * 64 * 32 * 4)

// ---------------- helpers ----------------------------------------------------
__device__ __forceinline__ float sigf(float x) { return 1.f / (1.f + expf(-x)); }

__device__ __forceinline__ unsigned short f2bf(float v) {
    __nv_bfloat16 h = __float2bfloat16(v);
    return __bfloat16_as_ushort(h);
}

// write one fp32 element (m,k) into plane-split A fragment layout
__device__ __forceinline__ void pack_elem(unsigned* dst, int KG, size_t po, int m, int k, float v) {
    int mg = m >> 4, ri = m & 15, kg = k >> 4, c = k & 15;
    int lane = ((ri & 7) << 2) + ((c & 7) >> 1);
    int reg  = (ri >> 3) + ((c >> 3) << 1);
    size_t base = (((size_t)mg * KG + kg) * 32 + lane) * 4 + reg;
    unsigned short hb = f2bf(v);
    float r = v - __bfloat162float(__ushort_as_bfloat16(hb));
    unsigned short lb = f2bf(r);
    ((unsigned short*)(dst + base))[c & 1] = hb;
    ((unsigned short*)(dst + po + base))[c & 1] = lb;
}

__device__ __forceinline__ void mma16816(float* c,
    unsigned a0, unsigned a1, unsigned a2, unsigned a3,
    unsigned b0, unsigned b1)
{
    asm volatile(
        "mma.sync.aligned.m16n8k16.row.col.f32.bf16.bf16.f32 "
        "{%0,%1,%2,%3}, {%4,%5,%6,%7}, {%8,%9}, {%0,%1,%2,%3};"
        : "+f"(c[0]), "+f"(c[1]), "+f"(c[2]), "+f"(c[3])
        : "r"(a0), "r"(a1), "r"(a2), "r"(a3), "r"(b0), "r"(b1));
}

__device__ __forceinline__ void cpa16(void* smem_ptr, const void* gptr) {
    unsigned sa = (unsigned)__cvta_generic_to_shared(smem_ptr);
    asm volatile("cp.async.cg.shared.global [%0], [%1], 16;" :: "r"(sa), "l"(gptr));
}
#define CP_COMMIT() asm volatile("cp.async.commit_group;" ::: "memory")
#define CP_WAIT(n)  asm volatile("cp.async.wait_group %0;" :: "n"(n) : "memory")

__device__ __forceinline__ void gridsync(unsigned nb) {
    __threadfence();
    __syncthreads();
    if (threadIdx.x == 0) {
        unsigned gen = g_bargen;
        if (atomicAdd(&g_barcnt, 1u) == nb - 1u) {
            g_barcnt = 0;
            __threadfence();
            g_bargen = gen + 1u;
        } else {
            while (g_bargen == gen) { }
        }
    }
    __syncthreads();
    __threadfence();
}

// ---------------- sort: stable argsort of -lengths ---------------------------
__global__ void k_sort(const int* __restrict__ lens) {
    int idx[Bb];
    for (int i = 0; i < Bb; i++) idx[i] = i;
    for (int i = 1; i < Bb; i++) {
        int v = idx[i];
        int kv = lens[v];
        int j = i - 1;
        while (j >= 0 && lens[idx[j]] < kv) { idx[j + 1] = idx[j]; j--; }
        idx[j + 1] = v;
    }
    for (int i = 0; i < Bb; i++) {
        g_order[i] = idx[i];
        g_lens_s[i] = lens[idx[i]];
    }
}

// ---------------- gathers (write directly into packed A layout) --------------
__global__ void k_gather_x(const int* __restrict__ mr, const float* __restrict__ emb) {
    int idx = blockIdx.x * 256 + threadIdx.x;           // over S*B*E
    int e = idx & (Ee - 1);
    int b = (idx >> 9) & (Bb - 1);
    int s = idx >> 15;
    int tok = mr[g_order[b] * Ss + s];
    float v = emb[(size_t)tok * Ee + e];
    pack_elem(g_xP, 32, PO_X, s * Bb + b, e, v);
}

__global__ void k_gather_tgt(const int* __restrict__ ref, const float* __restrict__ emb) {
    int idx = blockIdx.x * 256 + threadIdx.x;           // over T*B*E
    int e = idx & (Ee - 1);
    int b = (idx >> 9) & (Bb - 1);
    int t = idx >> 15;
    int tok = ref[g_order[b] * Tt + t];
    float v = emb[(size_t)tok * Ee + e];
    pack_elem(g_tgtP, 32, PO_TGT, t * Bb + b, e, v);
}

__global__ void k_init() {
    int idx = blockIdx.x * 256 + threadIdx.x;   // 32768 threads
    g_s[idx] = 0.f;
    g_m[idx] = 0.f;
    g_hP[idx] = 0u;
}

// ---------------- pack A weight (row-major fp32 -> A frag) -------------------
__global__ void k_packAw(const float* __restrict__ src, unsigned* __restrict__ dst,
                         int KG, size_t po) {
    int idx = blockIdx.x * 256 + threadIdx.x;
    int K = KG * 16;
    int m = idx / K, k = idx - m * K;
    pack_elem(dst, KG, po, m, k, src[idx]);
}

// ---------------- pack B matrices into fragment layout (general strides) -----
__global__ void k_packB(const float* __restrict__ s1, long sN1, long sK1,
                        const float* __restrict__ s2, long sN2, long sK2,
                        int ksplit, unsigned* __restrict__ dst, int KG)
{
    int idx = blockIdx.x * 256 + threadIdx.x;  // (ng*KG + kg)*32 + lane
    int lane = idx & 31;
    int kg = (idx >> 5) % KG;
    int ng = idx / (32 * KG);
    int n = ng * 8 + (lane >> 2);
    int k0 = kg * 16 + (lane & 3) * 2;
    float e[4];
    int ks[4] = { k0, k0 + 1, k0 + 8, k0 + 9 };
#pragma unroll
    for (int i = 0; i < 4; i++) {
        int k = ks[i];
        e[i] = (k >= ksplit) ? s2[(size_t)n * sN2 + (size_t)(k - ksplit) * sK2]
                             : s1[(size_t)n * sN1 + (size_t)k * sK1];
    }
    unsigned short hb[4], lb[4];
#pragma unroll
    for (int i = 0; i < 4; i++) {
        hb[i] = f2bf(e[i]);
        lb[i] = f2bf(e[i] - __bfloat162float(__ushort_as_bfloat16(hb[i])));
    }
    uint4 w;
    w.x = (unsigned)hb[0] | ((unsigned)hb[1] << 16);
    w.y = (unsigned)hb[2] | ((unsigned)hb[3] << 16);
    w.z = (unsigned)lb[0] | ((unsigned)lb[1] << 16);
    w.w = (unsigned)lb[2] | ((unsigned)lb[3] << 16);
    *(uint4*)(dst + (size_t)idx * 4) = w;
}

// ---------------- generic split-bf16 tensor-core GEMM (prep only) ------------
__global__ __launch_bounds__(256) void mma_gemm(
    const unsigned* __restrict__ AP, size_t poA,
    const unsigned* __restrict__ BP,
    const float* __restrict__ Add, int ldadd,
    float* __restrict__ C, int ldc, int KG)
{
    const int lane = threadIdx.x & 31;
    const int w = threadIdx.x >> 5;
    const int mg = blockIdx.y * 4 + (w & 3);
    const int ngBase = blockIdx.x * 8 + (w >> 2) * 4;

    float acc[4][4];
#pragma unroll
    for (int j = 0; j < 4; j++)
#pragma unroll
        for (int i = 0; i < 4; i++) acc[j][i] = 0.f;

    const unsigned* aPtr = AP + (((size_t)mg * KG) * 32 + lane) * 4;
    const unsigned* bPtr = BP + (((size_t)ngBase * KG) * 32 + lane) * 4;
    const size_t bNg = (size_t)KG * 128;

    for (int kg = 0; kg < KG; kg++) {
        uint4 ah = *(const uint4*)aPtr;
        uint4 al = *(const uint4*)(aPtr + poA);
        aPtr += 128;
#pragma unroll
        for (int j = 0; j < 4; j++) {
            uint4 bb = *(const uint4*)(bPtr + j * bNg);
            mma16816(acc[j], ah.x, ah.y, ah.z, ah.w, bb.x, bb.y);
            mma16816(acc[j], al.x, al.y, al.z, al.w, bb.x, bb.y);
            mma16816(acc[j], ah.x, ah.y, ah.z, ah.w, bb.z, bb.w);
        }
        bPtr += 128;
    }

    const int row = lane >> 2;
    const int col = (lane & 3) * 2;
    const int m0 = mg * 16 + row;
#pragma unroll
    for (int j = 0; j < 4; j++) {
        int n = (ngBase + j) * 8 + col;
        float v00 = acc[j][0], v01 = acc[j][1], v10 = acc[j][2], v11 = acc[j][3];
        if (Add) {
            v00 += Add[(size_t)m0 * ldadd + n];       v01 += Add[(size_t)m0 * ldadd + n + 1];
            v10 += Add[(size_t)(m0 + 8) * ldadd + n]; v11 += Add[(size_t)(m0 + 8) * ldadd + n + 1];
        }
        *(float2*)&C[(size_t)m0 * ldc + n] = make_float2(v00, v01);
        *(float2*)&C[(size_t)(m0 + 8) * ldc + n] = make_float2(v10, v11);
    }
}

// ---------------- persistent encoder: 128 steps of (gates mma + lstm) --------
__global__ __launch_bounds__(256) void k_encoder() {
    const int tid = threadIdx.x, lane = tid & 31, wid = tid >> 5;
    const int wg = blockIdx.x * 8 + wid;        // 0..1023
    const int ng = wg >> 2, mg = wg & 3;
    const unsigned* aBase = g_hP + (((size_t)mg * 32) * 32 + lane) * 4;
    const unsigned* bBase = g_WhhEP + (((size_t)ng * 32) * 32 + lane) * 4;
    const int r = lane >> 2, c2 = (lane & 3) * 2;
    const int m0 = mg * 16 + r;
    const int n = ng * 8 + c2;
    const int lidx = blockIdx.x * 256 + tid;    // 0..32767 = b*512+h
    const int b = lidx >> 9, h = lidx & 511;
    const unsigned nb = gridDim.x;

    for (int t = 0; t < Ss; t++) {
        float acc[4] = {0.f, 0.f, 0.f, 0.f};
        const unsigned* ap = aBase;
        const unsigned* bp = bBase;
#pragma unroll 4
        for (int kg = 0; kg < 32; kg++) {
            uint4 ah = *(const uint4*)ap;
            uint4 al = *(const uint4*)(ap + PO_H);
            uint4 bb = *(const uint4*)bp;
            mma16816(acc, ah.x, ah.y, ah.z, ah.w, bb.x, bb.y);
            mma16816(acc, al.x, al.y, al.z, al.w, bb.x, bb.y);
            mma16816(acc, ah.x, ah.y, ah.z, ah.w, bb.z, bb.w);
            ap += 128; bp += 128;
        }
        const float* xih = g_Xih + (size_t)t * Bb * G4;
        g_gates[(size_t)m0 * G4 + n]           = acc[0] + xih[(size_t)m0 * G4 + n];
        g_gates[(size_t)m0 * G4 + n + 1]       = acc[1] + xih[(size_t)m0 * G4 + n + 1];
        g_gates[(size_t)(m0 + 8) * G4 + n]     = acc[2] + xih[(size_t)(m0 + 8) * G4 + n];
        g_gates[(size_t)(m0 + 8) * G4 + n + 1] = acc[3] + xih[(size_t)(m0 + 8) * G4 + n + 1];
        gridsync(nb);

        const float* gg = g_gates + b * G4;
        float ig = sigf(gg[h]);
        float fg = sigf(gg[Hh + h]);
        float gd = tanhf(gg[2 * Hh + h]);
        float og = sigf(gg[3 * Hh + h]);
        float c_old = g_m[lidx];
        float c_new = fg * c_old + ig * gd;
        float h_new = og * tanhf(c_new);
        bool valid = t < g_lens_s[b];
        float h_old = g_s[lidx];
        float hcur = valid ? h_new : h_old;
        g_m[lidx] = valid ? c_new : c_old;
        g_s[lidx] = hcur;
        g_hs[((size_t)b * Ss + t) * Hh + h] = valid ? h_new : 0.f;
        pack_elem(g_hP, 32, PO_H, b, h, hcur);
        pack_elem(g_gAP, 64, PO_GA, b, Hh + h, hcur);
        gridsync(nb);
    }
}

// ---------------- att1 = tanh(hs @ W_a1^T) ------------------------------------
__global__ __launch_bounds__(256) void k_att1(const float* __restrict__ Wa1) {
    int w = blockIdx.x * 8 + (threadIdx.x >> 5);   // over B*S warps
    int lane = threadIdx.x & 31;
    int b = w >> 7, s = w & (Ss - 1);
    float acc = 0.f;
    const float* hr = g_hs + ((size_t)b * Ss + s) * Hh;
    for (int k = lane * 4; k < Hh; k += 128) {
        float4 hv = *(const float4*)(hr + k);
        float4 wv = *(const float4*)(Wa1 + k);
        acc += hv.x * wv.x + hv.y * wv.y + hv.z * wv.z + hv.w * wv.w;
    }
#pragma unroll
    for (int off = 16; off; off >>= 1) acc += __shfl_down_sync(0xffffffffu, acc, off);
    if (lane == 0) g_att1[b * Ss + s] = tanhf(acc);
}

// ---------------- final softmax + desort scatter (device body) ---------------
__device__ void smfinal_body(int b, int t, float* __restrict__ out,
                             float* s_red, int tid) {
    float mx = -1e30f;
    for (int i = tid; i < NTILES; i += 256) mx = fmaxf(mx, g_pmax[i * 64 + b]);
    s_red[tid] = mx; __syncthreads();
    for (int off = 128; off; off >>= 1) { if (tid < off) s_red[tid] = fmaxf(s_red[tid], s_red[tid + off]); __syncthreads(); }
    float gmax = s_red[0]; __syncthreads();
    float s = 0.f;
    for (int i = tid; i < NTILES; i += 256) s += g_psum[i * 64 + b] * __expf(g_pmax[i * 64 + b] - gmax);
    s_red[tid] = s; __syncthreads();
    for (int off = 128; off; off >>= 1) { if (tid < off) s_red[tid] += s_red[tid + off]; __syncthreads(); }
    float inv = 1.f / s_red[0];
    __syncthreads();
    const float* lg = g_logits + (size_t)b * Vv;
    float* dst = out + ((size_t)g_order[b] * Tt + t) * Vv;
    for (int v = tid; v < Vv; v += 256) dst[v] = __expf(lg[v] - gmax) * inv;
}

// ---------------- persistent fused decoder ------------------------------------
// dynamic smem: [A double-buffer: 2 x 64KB][B ring: 4 x 16KB] = 192KB
__global__ __launch_bounds__(256) void k_decoder(const float* __restrict__ Wa2,
                                                 const int* __restrict__ mr_len,
                                                 float* __restrict__ out) {
    extern __shared__ unsigned sm[];
    __shared__ float s_red[256];
    __shared__ float s_alph[Ss];
    __shared__ float s_a;
    const int tid = threadIdx.x, lane = tid & 31, wid = tid >> 5;
    const int bid = blockIdx.x;
    const unsigned nb = gridDim.x;
    const int tile0 = bid;
    const int tile1 = bid + DECB;

    for (int t = 0; t < Tt; t++) {
        // ---------- P0: attn (bid<64) || smfinal(t-1) (64<=bid<128) ----------
        if (bid < Bb) {
            const int b = bid;
            const float* sv = g_s + b * Hh;
            float p = 0.f;
            for (int k = tid; k < Hh; k += 256) p += sv[k] * Wa2[k];
            s_red[tid] = p; __syncthreads();
            for (int off = 128; off; off >>= 1) { if (tid < off) s_red[tid] += s_red[tid + off]; __syncthreads(); }
            if (tid == 0) s_a = tanhf(s_red[0]);
            __syncthreads();
            float a = s_a;
            float e = -1e30f;
            if (tid < Ss) {
                // reference bug preserved: UNSORTED lengths index sorted row
                int len = mr_len[b];
                e = (tid < len) ? g_att1[b * Ss + tid] * a : -1e9f;
            }
            s_red[tid] = e; __syncthreads();
            for (int off = 128; off; off >>= 1) { if (tid < off) s_red[tid] = fmaxf(s_red[tid], s_red[tid + off]); __syncthreads(); }
            float mx = s_red[0]; __syncthreads();
            float ex = (tid < Ss) ? __expf(e - mx) : 0.f;
            s_red[tid] = ex; __syncthreads();
            for (int off = 128; off; off >>= 1) { if (tid < off) s_red[tid] += s_red[tid + off]; __syncthreads(); }
            if (tid < Ss) s_alph[tid] = ex / s_red[0];
            __syncthreads();
            float cx = 0.f, cy = 0.f;
            const float2* hb = (const float2*)(g_hs + (size_t)b * Ss * Hh) + tid;
#pragma unroll 8
            for (int s2 = 0; s2 < Ss; s2++) {
                float av = s_alph[s2];
                float2 hv = hb[(size_t)s2 * (Hh / 2)];
                cx = fmaf(av, hv.x, cx);
                cy = fmaf(av, hv.y, cy);
            }
            int h0 = tid * 2;
            pack_elem(g_gAP, 64, PO_GA, b, h0, cx);
            pack_elem(g_gAP, 64, PO_GA, b, h0 + 1, cy);
            pack_elem(g_scP, 64, PO_SC, b, Hh + h0, cx);
            pack_elem(g_scP, 64, PO_SC, b, Hh + h0 + 1, cy);
        } else if (t > 0 && bid - Bb < Bb) {
            smfinal_body(bid - Bb, t - 1, out, s_red, tid);
        }
        gridsync(nb);

        // ---------- P1: gates = [ctx|s] @ [M2|Whh_d]^T + Gpre[t] ----------
        {
            int w = bid * 8 + wid;
            if (w < 1024) {
                int mg = w & 3, ng = w >> 2;
                float acc[4] = {0.f, 0.f, 0.f, 0.f};
                const unsigned* ap = g_gAP + (((size_t)mg * 64) * 32 + lane) * 4;
                const unsigned* bp = g_GcatP + (((size_t)ng * 64) * 32 + lane) * 4;
#pragma unroll 4
                for (int kg = 0; kg < 64; kg++) {
                    uint4 ah = *(const uint4*)ap;
                    uint4 al = *(const uint4*)(ap + PO_GA);
                    uint4 bb = *(const uint4*)bp;
                    mma16816(acc, ah.x, ah.y, ah.z, ah.w, bb.x, bb.y);
                    mma16816(acc, al.x, al.y, al.z, al.w, bb.x, bb.y);
                    mma16816(acc, ah.x, ah.y, ah.z, ah.w, bb.z, bb.w);
                    ap += 128; bp += 128;
                }
                int r = lane >> 2, cc = (lane & 3) * 2;
                int m0 = mg * 16 + r, n = ng * 8 + cc;
                const float* adp = g_Gpre + (size_t)t * Bb * G4;
                g_gates[(size_t)m0 * G4 + n]           = acc[0] + adp[(size_t)m0 * G4 + n];
                g_gates[(size_t)m0 * G4 + n + 1]       = acc[1] + adp[(size_t)m0 * G4 + n + 1];
                g_gates[(size_t)(m0 + 8) * G4 + n]     = acc[2] + adp[(size_t)(m0 + 8) * G4 + n];
                g_gates[(size_t)(m0 + 8) * G4 + n + 1] = acc[3] + adp[(size_t)(m0 + 8) * G4 + n + 1];
            }
        }
        gridsync(nb);

        // ---------- P2: lstm elementwise + pack ----------
        if (bid < 128) {
            int idx = bid * 256 + tid;
            int b = idx >> 9, h = idx & 511;
            const float* gg = g_gates + b * G4;
            float ig = sigf(gg[h]);
            float fg = sigf(gg[Hh + h]);
            float gd = tanhf(gg[2 * Hh + h]);
            float og = sigf(gg[3 * Hh + h]);
            float c_new = fg * g_m[idx] + ig * gd;
            float h_new = og * tanhf(c_new);
            g_m[idx] = c_new;
            g_s[idx] = h_new;
            pack_elem(g_scP, 64, PO_SC, b, h, h_new);
            pack_elem(g_gAP, 64, PO_GA, b, Hh + h, h_new);
        }
        gridsync(nb);

        // ---------- P3: logits tiles via cp.async pipeline + partial softmax ----
        {
            // A quarter prefetch into slot q&1 (64KB each)
            auto prefA = [&](int q) {
                unsigned* dst = sm + (q & 1) * 16384;
#pragma unroll
                for (int i = 0; i < 16; i++) {
                    int j = tid + i * 256;                   // (kgl,mg,p,lane)
                    int l2 = j & 31, p = (j >> 5) & 1, mg = (j >> 6) & 3, kgl = j >> 8;
                    const unsigned* src = g_scP + (size_t)p * PO_SC
                        + (((size_t)mg * 64 + q * 16 + kgl) * 32 + l2) * 4;
                    cpa16(dst + (size_t)j * 4, src);
                }
            };
            // B kg prefetch into ring slot kg&3 (16KB each)
            auto prefB = [&](int kg) {
                unsigned* dst = sm + 32768 + (kg & 3) * 4096;
#pragma unroll
                for (int i = 0; i < 4; i++) {
                    int j = tid + i * 256;                   // (t2,ngl,lane)
                    int l2 = j & 31, ngl = (j >> 5) & 15, t2 = j >> 9;
                    int tile = t2 ? tile1 : tile0;
                    if (tile < NTILES) {
                        const unsigned* src = g_WyP
                            + (((size_t)(tile * 16 + ngl) * 64 + kg) * 32 + l2) * 4;
                        cpa16(dst + (size_t)j * 4, src);
                    }
                }
            };

            float acc[2][2][4][4];
#pragma unroll
            for (int ts = 0; ts < 2; ts++)
#pragma unroll
                for (int j = 0; j < 2; j++)
#pragma unroll
                    for (int g = 0; g < 4; g++)
#pragma unroll
                        for (int i = 0; i < 4; i++) acc[ts][j][g][i] = 0.f;

            // prologue: A0, B0, B1, B2
            prefA(0); CP_COMMIT();
            prefB(0); CP_COMMIT();
            prefB(1); CP_COMMIT();
            prefB(2); CP_COMMIT();

            const bool two = (tile1 < NTILES);
            for (int kg = 0; kg < 64; kg++) {
                CP_WAIT(2);
                __syncthreads();
                // issue next prefetches (always commit for uniform counting)
                if (kg + 3 < 64) prefB(kg + 3);
                CP_COMMIT();
                if ((kg & 15) == 12) {
                    if (kg + 4 < 64) prefA((kg + 4) >> 4);
                    CP_COMMIT();
                }

                const unsigned* sa = sm + ((kg >> 4) & 1) * 16384;
                const unsigned* sb = sm + 32768 + (kg & 3) * 4096;
                const int kgl = kg & 15;
                uint4 ah[4], al[4];
#pragma unroll
                for (int mg = 0; mg < 4; mg++) {
                    const unsigned* ap = sa + (((size_t)(kgl * 4 + mg) * 2) * 32 + lane) * 4;
                    ah[mg] = *(const uint4*)ap;
                    al[mg] = *(const uint4*)(ap + 128);
                }
                {
                    uint4 bb0 = *(const uint4*)(sb + (((size_t)(wid * 2)) * 32 + lane) * 4);
                    uint4 bb1 = *(const uint4*)(sb + (((size_t)(wid * 2 + 1)) * 32 + lane) * 4);
#pragma unroll
                    for (int mg = 0; mg < 4; mg++) {
                        mma16816(acc[0][0][mg], ah[mg].x, ah[mg].y, ah[mg].z, ah[mg].w, bb0.x, bb0.y);
                        mma16816(acc[0][0][mg], al[mg].x, al[mg].y, al[mg].z, al[mg].w, bb0.x, bb0.y);
                        mma16816(acc[0][0][mg], ah[mg].x, ah[mg].y, ah[mg].z, ah[mg].w, bb0.z, bb0.w);
                        mma16816(acc[0][1][mg], ah[mg].x, ah[mg].y, ah[mg].z, ah[mg].w, bb1.x, bb1.y);
                        mma16816(acc[0][1][mg], al[mg].x, al[mg].y, al[mg].z, al[mg].w, bb1.x, bb1.y);
                        mma16816(acc[0][1][mg], ah[mg].x, ah[mg].y, ah[mg].z, ah[mg].w, bb1.z, bb1.w);
                    }
                }
                if (two) {
                    uint4 bb0 = *(const uint4*)(sb + (((size_t)(16 + wid * 2)) * 32 + lane) * 4);
                    uint4 bb1 = *(const uint4*)(sb + (((size_t)(16 + wid * 2 + 1)) * 32 + lane) * 4);
#pragma unroll
                    for (int mg = 0; mg < 4; mg++) {
                        mma16816(acc[1][0][mg], ah[mg].x, ah[mg].y, ah[mg].z, ah[mg].w, bb0.x, bb0.y);
                        mma16816(acc[1][0][mg], al[mg].x, al[mg].y, al[mg].z, al[mg].w, bb0.x, bb0.y);
                        mma16816(acc[1][0][mg], ah[mg].x, ah[mg].y, ah[mg].z, ah[mg].w, bb0.z, bb0.w);
                        mma16816(acc[1][1][mg], ah[mg].x, ah[mg].y, ah[mg].z, ah[mg].w, bb1.x, bb1.y);
                        mma16816(acc[1][1][mg], al[mg].x, al[mg].y, al[mg].z, al[mg].w, bb1.x, bb1.y);
                        mma16816(acc[1][1][mg], ah[mg].x, ah[mg].y, ah[mg].z, ah[mg].w, bb1.z, bb1.w);
                    }
                }
            }
            CP_WAIT(0);
            __syncthreads();

            // epilogue per tile: write logits + row partials (reuse sm as float buf)
            float* sb = (float*)sm;
            const int r = lane >> 2, c = (lane & 3) * 2;
#pragma unroll
            for (int ts = 0; ts < 2; ts++) {
                int tile = ts ? tile1 : tile0;
                if (tile >= NTILES) break;
                __syncthreads();
#pragma unroll
                for (int j = 0; j < 2; j++) {
                    int ccol = wid * 16 + j * 8 + c;
#pragma unroll
                    for (int mg = 0; mg < 4; mg++) {
                        int m0 = mg * 16 + r;
                        float v0 = acc[ts][j][mg][0], v1 = acc[ts][j][mg][1];
                        float v2 = acc[ts][j][mg][2], v3 = acc[ts][j][mg][3];
                        sb[m0 * 132 + ccol] = v0;       sb[m0 * 132 + ccol + 1] = v1;
                        sb[(m0 + 8) * 132 + ccol] = v2; sb[(m0 + 8) * 132 + ccol + 1] = v3;
                        size_t g = (size_t)m0 * Vv + (size_t)tile * 128 + ccol;
                        *(float2*)&g_logits[g] = make_float2(v0, v1);
                        *(float2*)&g_logits[g + (size_t)8 * Vv] = make_float2(v2, v3);
                    }
                }
                __syncthreads();
                int row = tid >> 2, seg = tid & 3;
                float mx2 = -1e30f;
#pragma unroll 8
                for (int i = 0; i < 32; i++) mx2 = fmaxf(mx2, sb[row * 132 + seg + i * 4]);
                mx2 = fmaxf(mx2, __shfl_xor_sync(0xffffffffu, mx2, 1));
                mx2 = fmaxf(mx2, __shfl_xor_sync(0xffffffffu, mx2, 2));
                float sm2 = 0.f;
#pragma unroll 8
                for (int i = 0; i < 32; i++) sm2 += __expf(sb[row * 132 + seg + i * 4] - mx2);
                sm2 += __shfl_xor_sync(0xffffffffu, sm2, 1);
                sm2 += __shfl_xor_sync(0xffffffffu, sm2, 2);
                if (seg == 0) { g_pmax[tile * 64 + row] = mx2; g_psum[tile * 64 + row] = sm2; }
            }
        }
        gridsync(nb);
    }

    // final scatter for t = Tt-1
    if (bid >= Bb && bid - Bb < Bb) smfinal_body(bid - Bb, Tt - 1, out, s_red, tid);
}

// ---------------- launch -------------------------------------------------------
extern "C" void kernel_launch(void* const* d_in, const int* in_sizes, int n_in,
                              void* d_out, int out_size) {
    const int*   mr    = (const int*)d_in[0];
    const int*   ref   = (const int*)d_in[1];
    const int*   lens  = (const int*)d_in[2];
    const float* emb   = (const float*)d_in[3];
    const float* Wih_e = (const float*)d_in[4];
    const float* Whh_e = (const float*)d_in[5];
    const float* Wih_d = (const float*)d_in[6];
    const float* Whh_d = (const float*)d_in[7];
    const float* Wy    = (const float*)d_in[8];
    const float* Ws    = (const float*)d_in[9];
    const float* Wa1   = (const float*)d_in[10];
    const float* Wa2   = (const float*)d_in[11];
    float* out = (float*)d_out;

    float *p_Xih, *p_Gpre, *p_M12;
    unsigned *p_WyP, *p_GcatP, *p_WhhEP, *p_WihEP, *p_WsTP, *p_M1P, *p_WihdA;
    unsigned *p_xP, *p_tgtP;
    cudaGetSymbolAddress((void**)&p_Xih,    g_Xih);
    cudaGetSymbolAddress((void**)&p_Gpre,   g_Gpre);
    cudaGetSymbolAddress((void**)&p_M12,    g_M12);
    cudaGetSymbolAddress((void**)&p_WyP,    g_WyP);
    cudaGetSymbolAddress((void**)&p_GcatP,  g_GcatP);
    cudaGetSymbolAddress((void**)&p_WhhEP,  g_WhhEP);
    cudaGetSymbolAddress((void**)&p_WihEP,  g_WihEP);
    cudaGetSymbolAddress((void**)&p_WsTP,   g_WsTP);
    cudaGetSymbolAddress((void**)&p_M1P,    g_M1P);
    cudaGetSymbolAddress((void**)&p_WihdA,  g_WihdA);
    cudaGetSymbolAddress((void**)&p_xP,     g_xP);
    cudaGetSymbolAddress((void**)&p_tgtP,   g_tgtP);

    cudaFuncSetAttribute(k_decoder, cudaFuncAttributeMaxDynamicSharedMemorySize, 196608);

    // ---- prep ----
    k_sort<<<1, 1>>>(lens);
    k_gather_x<<<(Ss * Bb * Ee) / 256, 256>>>(mr, emb);
    k_gather_tgt<<<(Tt * Bb * Ee) / 256, 256>>>(ref, emb);
    k_init<<<128, 256>>>();

    // weight packs
    k_packB<<<32000, 256>>>(Wy, 1024, 1, Wy, 0, 0, 1 << 28, p_WyP, 64);
    k_packB<<<1024, 256>>>(Whh_e, 512, 1, Whh_e, 0, 0, 1 << 28, p_WhhEP, 32);
    k_packB<<<1024, 256>>>(Wih_e, 512, 1, Wih_e, 0, 0, 1 << 28, p_WihEP, 32);
    k_packB<<<512, 256>>>(Ws, 1, 1024, Ws, 0, 0, 1 << 28, p_WsTP, 32);   // Ws^T
    k_packAw<<<4096, 256>>>(Wih_d, p_WihdA, 32, PO_WIHD);

    // M12 = Wih_d @ Ws  [2048 x 1024]
    mma_gemm<<<dim3(16, 32), 256>>>(p_WihdA, PO_WIHD, p_WsTP, nullptr, 0, p_M12, KD, 32);
    k_packB<<<1024, 256>>>(p_M12, 1024, 1, p_M12, 0, 0, 1 << 28, p_M1P, 32);
    k_packB<<<2048, 256>>>(p_M12 + 512, 1024, 1, Whh_d, 512, 1, 512, p_GcatP, 64);

    // Xih = x @ W_ih_enc^T  [8192 x 2048]
    mma_gemm<<<dim3(32, 128), 256>>>(p_xP, PO_X, p_WihEP, nullptr, 0, p_Xih, G4, 32);
    // Gpre = tgt @ M1^T  [3072 x 2048]
    mma_gemm<<<dim3(32, 48), 256>>>(p_tgtP, PO_TGT, p_M1P, nullptr, 0, p_Gpre, G4, 32);

    // ---- encoder (persistent) ----
    k_encoder<<<128, 256>>>();

    k_att1<<<(Bb * Ss) / 8, 256>>>(Wa1);

    // ---- decoder (single persistent kernel) ----
    k_decoder<<<DECB, 256, 196608>>>(Wa2, lens, out);
}

// round 6
// speedup vs baseline: 2.5999x; 1.0058x over previous
#include <cuda_runtime.h>
#include <cuda_bf16.h>
#include <math.h>

// Problem constants
#define Vv 32000
#define Hh 512
#define Ee 512
#define Bb 64
#define Ss 128
#define Tt 48
#define G4 2048   // 4*H
#define KD 1024   // E+H == 2H
#define NTILES 250   // logits tiles of 128 cols
#define DECB 148     // persistent decoder blocks (<= SM count)

// ---------------- scratch (static device memory; no allocations) -------------
__device__ float g_Xih[Ss * Bb * G4];    // x @ W_ih_enc^T, [s][b][4H]
__device__ float g_Gpre[Tt * Bb * G4];   // tgt @ M1^T (y-part of decoder gates)
__device__ float g_hs[Bb * Ss * Hh];     // encoder hidden states [b][s][h]
__device__ float g_att1[Bb * Ss];        // tanh(hs @ W_a1^T)
__device__ float g_gates[Bb * G4];       // per-step LSTM gates
__device__ float g_logits[Bb * Vv];      // per-step logits
__device__ float g_s[Bb * Hh];           // hidden state fp32 (attn reads)
__device__ float g_m[Bb * Hh];           // cell state
__device__ float g_M12[G4 * KD];         // [M1 | M2] = Wih_d @ Ws  (fp32)
__device__ float g_pmax[NTILES * Bb];
__device__ float g_psum[NTILES * Bb];
__device__ int   g_order[Bb];
__device__ int   g_lens_s[Bb];

// grid barrier
__device__ unsigned g_barcnt = 0;
__device__ volatile unsigned g_bargen = 0;

// ---- packed bf16 split fragment buffers (PLANE-SPLIT layout) ----
// A layout: plane p in {hi,lo}: [p][mg][kg][lane][4] u32; lane stride 16B (coalesced)
// B layout: [ng][kg][lane][4] u32  (hi0,hi1,lo0,lo1 per lane; 16B contiguous)
__device__ unsigned g_WyP [4000u * 64 * 32 * 4];   // Wy    N=32000 K=1024
__device__ unsigned g_GcatP[256u * 64 * 32 * 4];   // [M2|Whh_d] N=2048 K=1024
__device__ unsigned g_WhhEP[256u * 32 * 32 * 4];   // Whh_enc N=2048 K=512
__device__ unsigned g_WihEP[256u * 32 * 32 * 4];   // Wih_enc N=2048 K=512
__device__ unsigned g_WsTP [128u * 32 * 32 * 4];   // Ws^T   N=1024 K=512
__device__ unsigned g_M1P  [256u * 32 * 32 * 4];   // M1     N=2048 K=512
__device__ unsigned g_WihdA[128u * 32 * 32 * 8];   // Wih_d A-layout M=2048 K=512
__device__ unsigned g_xP  [512u * 32 * 32 * 8];    // x    M=8192 K=512
__device__ unsigned g_tgtP[192u * 32 * 32 * 8];    // tgt  M=3072 K=512
__device__ unsigned g_hP  [  4u * 32 * 32 * 8];    // enc h M=64 K=512
__device__ unsigned g_gAP [  4u * 64 * 32 * 8];    // [ctx|s] M=64 K=1024 (gates A)
__device__ unsigned g_scP [  4u * 64 * 32 * 8];    // [s_new|ctx] M=64 K=1024 (logits A)

// plane offsets (in u32 words) = half of each A buffer
#define PO_WIHD ((size_t)128u * 32 * 32 * 4)
#define PO_X    ((size_t)512u * 32 * 32 * 4)
#define PO_TGT  ((size_t)192u * 32 * 32 * 4)
#define PO_H    ((size_t)4u * 32 * 32 * 4)
#define PO_GA   ((size_t)4u * 64 * 32 * 4)
#define PO_SC   ((size_t)4u * 64 * 32 * 4)

// ---------------- helpers ----------------------------------------------------
__device__ __forceinline__ float sigf(float x) { return 1.f / (1.f + expf(-x)); }

__device__ __forceinline__ unsigned short f2bf(float v) {
    __nv_bfloat16 h = __float2bfloat16(v);
    return __bfloat16_as_ushort(h);
}

// write one fp32 element (m,k) into plane-split A fragment layout
__device__ __forceinline__ void pack_elem(unsigned* dst, int KG, size_t po, int m, int k, float v) {
    int mg = m >> 4, ri = m & 15, kg = k >> 4, c = k & 15;
    int lane = ((ri & 7) << 2) + ((c & 7) >> 1);
    int reg  = (ri >> 3) + ((c >> 3) << 1);
    size_t base = (((size_t)mg * KG + kg) * 32 + lane) * 4 + reg;
    unsigned short hb = f2bf(v);
    float r = v - __bfloat162float(__ushort_as_bfloat16(hb));
    unsigned short lb = f2bf(r);
    ((unsigned short*)(dst + base))[c & 1] = hb;
    ((unsigned short*)(dst + po + base))[c & 1] = lb;
}

__device__ __forceinline__ void mma16816(float* c,
    unsigned a0, unsigned a1, unsigned a2, unsigned a3,
    unsigned b0, unsigned b1)
{
    asm volatile(
        "mma.sync.aligned.m16n8k16.row.col.f32.bf16.bf16.f32 "
        "{%0,%1,%2,%3}, {%4,%5,%6,%7}, {%8,%9}, {%0,%1,%2,%3};"
        : "+f"(c[0]), "+f"(c[1]), "+f"(c[2]), "+f"(c[3])
        : "r"(a0), "r"(a1), "r"(a2), "r"(a3), "r"(b0), "r"(b1));
}

__device__ __forceinline__ void cpa16(void* smem_ptr, const void* gptr) {
    unsigned sa = (unsigned)__cvta_generic_to_shared(smem_ptr);
    asm volatile("cp.async.cg.shared.global [%0], [%1], 16;" :: "r"(sa), "l"(gptr));
}
#define CP_COMMIT() asm volatile("cp.async.commit_group;" ::: "memory")
#define CP_WAIT(n)  asm volatile("cp.async.wait_group %0;" :: "n"(n) : "memory")

__device__ __forceinline__ void gridsync(unsigned nb) {
    __threadfence();
    __syncthreads();
    if (threadIdx.x == 0) {
        unsigned gen = g_bargen;
        if (atomicAdd(&g_barcnt, 1u) == nb - 1u) {
            g_barcnt = 0;
            __threadfence();
            g_bargen = gen + 1u;
        } else {
            while (g_bargen == gen) { }
        }
    }
    __syncthreads();
    __threadfence();
}

// ---------------- sort: stable argsort of -lengths ---------------------------
__global__ void k_sort(const int* __restrict__ lens) {
    int idx[Bb];
    for (int i = 0; i < Bb; i++) idx[i] = i;
    for (int i = 1; i < Bb; i++) {
        int v = idx[i];
        int kv = lens[v];
        int j = i - 1;
        while (j >= 0 && lens[idx[j]] < kv) { idx[j + 1] = idx[j]; j--; }
        idx[j + 1] = v;
    }
    for (int i = 0; i < Bb; i++) {
        g_order[i] = idx[i];
        g_lens_s[i] = lens[idx[i]];
    }
}

// ---------------- gathers (write directly into packed A layout) --------------
__global__ void k_gather_x(const int* __restrict__ mr, const float* __restrict__ emb) {
    int idx = blockIdx.x * 256 + threadIdx.x;           // over S*B*E
    int e = idx & (Ee - 1);
    int b = (idx >> 9) & (Bb - 1);
    int s = idx >> 15;
    int tok = mr[g_order[b] * Ss + s];
    float v = emb[(size_t)tok * Ee + e];
    pack_elem(g_xP, 32, PO_X, s * Bb + b, e, v);
}

__global__ void k_gather_tgt(const int* __restrict__ ref, const float* __restrict__ emb) {
    int idx = blockIdx.x * 256 + threadIdx.x;           // over T*B*E
    int e = idx & (Ee - 1);
    int b = (idx >> 9) & (Bb - 1);
    int t = idx >> 15;
    int tok = ref[g_order[b] * Tt + t];
    float v = emb[(size_t)tok * Ee + e];
    pack_elem(g_tgtP, 32, PO_TGT, t * Bb + b, e, v);
}

__global__ void k_init() {
    int idx = blockIdx.x * 256 + threadIdx.x;   // 32768 threads
    g_s[idx] = 0.f;
    g_m[idx] = 0.f;
    g_hP[idx] = 0u;
}

// ---------------- pack A weight (row-major fp32 -> A frag) -------------------
__global__ void k_packAw(const float* __restrict__ src, unsigned* __restrict__ dst,
                         int KG, size_t po) {
    int idx = blockIdx.x * 256 + threadIdx.x;
    int K = KG * 16;
    int m = idx / K, k = idx - m * K;
    pack_elem(dst, KG, po, m, k, src[idx]);
}

// ---------------- pack B matrices into fragment layout (general strides) -----
__global__ void k_packB(const float* __restrict__ s1, long sN1, long sK1,
                        const float* __restrict__ s2, long sN2, long sK2,
                        int ksplit, unsigned* __restrict__ dst, int KG)
{
    int idx = blockIdx.x * 256 + threadIdx.x;  // (ng*KG + kg)*32 + lane
    int lane = idx & 31;
    int kg = (idx >> 5) % KG;
    int ng = idx / (32 * KG);
    int n = ng * 8 + (lane >> 2);
    int k0 = kg * 16 + (lane & 3) * 2;
    float e[4];
    int ks[4] = { k0, k0 + 1, k0 + 8, k0 + 9 };
#pragma unroll
    for (int i = 0; i < 4; i++) {
        int k = ks[i];
        e[i] = (k >= ksplit) ? s2[(size_t)n * sN2 + (size_t)(k - ksplit) * sK2]
                             : s1[(size_t)n * sN1 + (size_t)k * sK1];
    }
    unsigned short hb[4], lb[4];
#pragma unroll
    for (int i = 0; i < 4; i++) {
        hb[i] = f2bf(e[i]);
        lb[i] = f2bf(e[i] - __bfloat162float(__ushort_as_bfloat16(hb[i])));
    }
    uint4 w;
    w.x = (unsigned)hb[0] | ((unsigned)hb[1] << 16);
    w.y = (unsigned)hb[2] | ((unsigned)hb[3] << 16);
    w.z = (unsigned)lb[0] | ((unsigned)lb[1] << 16);
    w.w = (unsigned)lb[2] | ((unsigned)lb[3] << 16);
    *(uint4*)(dst + (size_t)idx * 4) = w;
}

// ---------------- generic split-bf16 tensor-core GEMM (prep only) ------------
__global__ __launch_bounds__(256) void mma_gemm(
    const unsigned* __restrict__ AP, size_t poA,
    const unsigned* __restrict__ BP,
    const float* __restrict__ Add, int ldadd,
    float* __restrict__ C, int ldc, int KG)
{
    const int lane = threadIdx.x & 31;
    const int w = threadIdx.x >> 5;
    const int mg = blockIdx.y * 4 + (w & 3);
    const int ngBase = blockIdx.x * 8 + (w >> 2) * 4;

    float acc[4][4];
#pragma unroll
    for (int j = 0; j < 4; j++)
#pragma unroll
        for (int i = 0; i < 4; i++) acc[j][i] = 0.f;

    const unsigned* aPtr = AP + (((size_t)mg * KG) * 32 + lane) * 4;
    const unsigned* bPtr = BP + (((size_t)ngBase * KG) * 32 + lane) * 4;
    const size_t bNg = (size_t)KG * 128;

    for (int kg = 0; kg < KG; kg++) {
        uint4 ah = *(const uint4*)aPtr;
        uint4 al = *(const uint4*)(aPtr + poA);
        aPtr += 128;
#pragma unroll
        for (int j = 0; j < 4; j++) {
            uint4 bb = *(const uint4*)(bPtr + j * bNg);
            mma16816(acc[j], ah.x, ah.y, ah.z, ah.w, bb.x, bb.y);
            mma16816(acc[j], al.x, al.y, al.z, al.w, bb.x, bb.y);
            mma16816(acc[j], ah.x, ah.y, ah.z, ah.w, bb.z, bb.w);
        }
        bPtr += 128;
    }

    const int row = lane >> 2;
    const int col = (lane & 3) * 2;
    const int m0 = mg * 16 + row;
#pragma unroll
    for (int j = 0; j < 4; j++) {
        int n = (ngBase + j) * 8 + col;
        float v00 = acc[j][0], v01 = acc[j][1], v10 = acc[j][2], v11 = acc[j][3];
        if (Add) {
            v00 += Add[(size_t)m0 * ldadd + n];       v01 += Add[(size_t)m0 * ldadd + n + 1];
            v10 += Add[(size_t)(m0 + 8) * ldadd + n]; v11 += Add[(size_t)(m0 + 8) * ldadd + n + 1];
        }
        *(float2*)&C[(size_t)m0 * ldc + n] = make_float2(v00, v01);
        *(float2*)&C[(size_t)(m0 + 8) * ldc + n] = make_float2(v10, v11);
    }
}

// ---------------- persistent encoder: 128 steps of (gates mma + lstm) --------
__global__ __launch_bounds__(256) void k_encoder() {
    const int tid = threadIdx.x, lane = tid & 31, wid = tid >> 5;
    const int wg = blockIdx.x * 8 + wid;        // 0..1023
    const int ng = wg >> 2, mg = wg & 3;
    const unsigned* aBase = g_hP + (((size_t)mg * 32) * 32 + lane) * 4;
    const unsigned* bBase = g_WhhEP + (((size_t)ng * 32) * 32 + lane) * 4;
    const int r = lane >> 2, c2 = (lane & 3) * 2;
    const int m0 = mg * 16 + r;
    const int n = ng * 8 + c2;
    const int lidx = blockIdx.x * 256 + tid;    // 0..32767 = b*512+h
    const int b = lidx >> 9, h = lidx & 511;
    const unsigned nb = gridDim.x;

    for (int t = 0; t < Ss; t++) {
        float acc[4] = {0.f, 0.f, 0.f, 0.f};
        const unsigned* ap = aBase;
        const unsigned* bp = bBase;
#pragma unroll 4
        for (int kg = 0; kg < 32; kg++) {
            uint4 ah = *(const uint4*)ap;
            uint4 al = *(const uint4*)(ap + PO_H);
            uint4 bb = *(const uint4*)bp;
            mma16816(acc, ah.x, ah.y, ah.z, ah.w, bb.x, bb.y);
            mma16816(acc, al.x, al.y, al.z, al.w, bb.x, bb.y);
            mma16816(acc, ah.x, ah.y, ah.z, ah.w, bb.z, bb.w);
            ap += 128; bp += 128;
        }
        const float* xih = g_Xih + (size_t)t * Bb * G4;
        g_gates[(size_t)m0 * G4 + n]           = acc[0] + xih[(size_t)m0 * G4 + n];
        g_gates[(size_t)m0 * G4 + n + 1]       = acc[1] + xih[(size_t)m0 * G4 + n + 1];
        g_gates[(size_t)(m0 + 8) * G4 + n]     = acc[2] + xih[(size_t)(m0 + 8) * G4 + n];
        g_gates[(size_t)(m0 + 8) * G4 + n + 1] = acc[3] + xih[(size_t)(m0 + 8) * G4 + n + 1];
        gridsync(nb);

        const float* gg = g_gates + b * G4;
        float ig = sigf(gg[h]);
        float fg = sigf(gg[Hh + h]);
        float gd = tanhf(gg[2 * Hh + h]);
        float og = sigf(gg[3 * Hh + h]);
        float c_old = g_m[lidx];
        float c_new = fg * c_old + ig * gd;
        float h_new = og * tanhf(c_new);
        bool valid = t < g_lens_s[b];
        float h_old = g_s[lidx];
        float hcur = valid ? h_new : h_old;
        g_m[lidx] = valid ? c_new : c_old;
        g_s[lidx] = hcur;
        g_hs[((size_t)b * Ss + t) * Hh + h] = valid ? h_new : 0.f;
        pack_elem(g_hP, 32, PO_H, b, h, hcur);
        pack_elem(g_gAP, 64, PO_GA, b, Hh + h, hcur);
        gridsync(nb);
    }
}

// ---------------- att1 = tanh(hs @ W_a1^T) ------------------------------------
__global__ __launch_bounds__(256) void k_att1(const float* __restrict__ Wa1) {
    int w = blockIdx.x * 8 + (threadIdx.x >> 5);   // over B*S warps
    int lane = threadIdx.x & 31;
    int b = w >> 7, s = w & (Ss - 1);
    float acc = 0.f;
    const float* hr = g_hs + ((size_t)b * Ss + s) * Hh;
    for (int k = lane * 4; k < Hh; k += 128) {
        float4 hv = *(const float4*)(hr + k);
        float4 wv = *(const float4*)(Wa1 + k);
        acc += hv.x * wv.x + hv.y * wv.y + hv.z * wv.z + hv.w * wv.w;
    }
#pragma unroll
    for (int off = 16; off; off >>= 1) acc += __shfl_down_sync(0xffffffffu, acc, off);
    if (lane == 0) g_att1[b * Ss + s] = tanhf(acc);
}

// ---------------- final softmax + desort scatter (device body) ---------------
__device__ void smfinal_body(int b, int t, float* __restrict__ out,
                             float* s_red, int tid) {
    float mx = -1e30f;
    for (int i = tid; i < NTILES; i += 256) mx = fmaxf(mx, g_pmax[i * 64 + b]);
    s_red[tid] = mx; __syncthreads();
    for (int off = 128; off; off >>= 1) { if (tid < off) s_red[tid] = fmaxf(s_red[tid], s_red[tid + off]); __syncthreads(); }
    float gmax = s_red[0]; __syncthreads();
    float s = 0.f;
    for (int i = tid; i < NTILES; i += 256) s += g_psum[i * 64 + b] * __expf(g_pmax[i * 64 + b] - gmax);
    s_red[tid] = s; __syncthreads();
    for (int off = 128; off; off >>= 1) { if (tid < off) s_red[tid] += s_red[tid + off]; __syncthreads(); }
    float inv = 1.f / s_red[0];
    __syncthreads();
    const float* lg = g_logits + (size_t)b * Vv;
    float* dst = out + ((size_t)g_order[b] * Tt + t) * Vv;
    for (int v = tid; v < Vv; v += 256) dst[v] = __expf(lg[v] - gmax) * inv;
}

// ---------------- persistent fused decoder ------------------------------------
// dynamic smem: [A double-buffer: 2 x 64KB][B ring: 4 x 16KB] = 192KB
__global__ __launch_bounds__(256) void k_decoder(const float* __restrict__ Wa2,
                                                 const int* __restrict__ mr_len,
                                                 float* __restrict__ out) {
    extern __shared__ unsigned sm[];
    __shared__ float s_red[256];
    __shared__ float s_alph[Ss];
    __shared__ float s_a;
    const int tid = threadIdx.x, lane = tid & 31, wid = tid >> 5;
    const int bid = blockIdx.x;
    const unsigned nb = gridDim.x;
    const int tile0 = bid;
    const int tile1 = bid + DECB;

    for (int t = 0; t < Tt; t++) {
        // ---------- P0: attn (bid<64) || smfinal(t-1) (64<=bid<128) ----------
        if (bid < Bb) {
            const int b = bid;
            const float* sv = g_s + b * Hh;
            float p = 0.f;
            for (int k = tid; k < Hh; k += 256) p += sv[k] * Wa2[k];
            s_red[tid] = p; __syncthreads();
            for (int off = 128; off; off >>= 1) { if (tid < off) s_red[tid] += s_red[tid + off]; __syncthreads(); }
            if (tid == 0) s_a = tanhf(s_red[0]);
            __syncthreads();
            float a = s_a;
            float e = -1e30f;
            if (tid < Ss) {
                // reference bug preserved: UNSORTED lengths index sorted row
                int len = mr_len[b];
                e = (tid < len) ? g_att1[b * Ss + tid] * a : -1e9f;
            }
            s_red[tid] = e; __syncthreads();
            for (int off = 128; off; off >>= 1) { if (tid < off) s_red[tid] = fmaxf(s_red[tid], s_red[tid + off]); __syncthreads(); }
            float mx = s_red[0]; __syncthreads();
            float ex = (tid < Ss) ? __expf(e - mx) : 0.f;
            s_red[tid] = ex; __syncthreads();
            for (int off = 128; off; off >>= 1) { if (tid < off) s_red[tid] += s_red[tid + off]; __syncthreads(); }
            if (tid < Ss) s_alph[tid] = ex / s_red[0];
            __syncthreads();
            float cx = 0.f, cy = 0.f;
            const float2* hb = (const float2*)(g_hs + (size_t)b * Ss * Hh) + tid;
#pragma unroll 8
            for (int s2 = 0; s2 < Ss; s2++) {
                float av = s_alph[s2];
                float2 hv = hb[(size_t)s2 * (Hh / 2)];
                cx = fmaf(av, hv.x, cx);
                cy = fmaf(av, hv.y, cy);
            }
            int h0 = tid * 2;
            pack_elem(g_gAP, 64, PO_GA, b, h0, cx);
            pack_elem(g_gAP, 64, PO_GA, b, h0 + 1, cy);
            pack_elem(g_scP, 64, PO_SC, b, Hh + h0, cx);
            pack_elem(g_scP, 64, PO_SC, b, Hh + h0 + 1, cy);
        } else if (t > 0 && bid - Bb < Bb) {
            smfinal_body(bid - Bb, t - 1, out, s_red, tid);
        }
        gridsync(nb);

        // ---------- P1: gates = [ctx|s] @ [M2|Whh_d]^T + Gpre[t] ----------
        {
            int w = bid * 8 + wid;
            if (w < 1024) {
                int mg = w & 3, ng = w >> 2;
                float acc[4] = {0.f, 0.f, 0.f, 0.f};
                const unsigned* ap = g_gAP + (((size_t)mg * 64) * 32 + lane) * 4;
                const unsigned* bp = g_GcatP + (((size_t)ng * 64) * 32 + lane) * 4;
#pragma unroll 4
                for (int kg = 0; kg < 64; kg++) {
                    uint4 ah = *(const uint4*)ap;
                    uint4 al = *(const uint4*)(ap + PO_GA);
                    uint4 bb = *(const uint4*)bp;
                    mma16816(acc, ah.x, ah.y, ah.z, ah.w, bb.x, bb.y);
                    mma16816(acc, al.x, al.y, al.z, al.w, bb.x, bb.y);
                    mma16816(acc, ah.x, ah.y, ah.z, ah.w, bb.z, bb.w);
                    ap += 128; bp += 128;
                }
                int r = lane >> 2, cc = (lane & 3) * 2;
                int m0 = mg * 16 + r, n = ng * 8 + cc;
                const float* adp = g_Gpre + (size_t)t * Bb * G4;
                g_gates[(size_t)m0 * G4 + n]           = acc[0] + adp[(size_t)m0 * G4 + n];
                g_gates[(size_t)m0 * G4 + n + 1]       = acc[1] + adp[(size_t)m0 * G4 + n + 1];
                g_gates[(size_t)(m0 + 8) * G4 + n]     = acc[2] + adp[(size_t)(m0 + 8) * G4 + n];
                g_gates[(size_t)(m0 + 8) * G4 + n + 1] = acc[3] + adp[(size_t)(m0 + 8) * G4 + n + 1];
            }
        }
        gridsync(nb);

        // ---------- P2: lstm elementwise + pack ----------
        if (bid < 128) {
            int idx = bid * 256 + tid;
            int b = idx >> 9, h = idx & 511;
            const float* gg = g_gates + b * G4;
            float ig = sigf(gg[h]);
            float fg = sigf(gg[Hh + h]);
            float gd = tanhf(gg[2 * Hh + h]);
            float og = sigf(gg[3 * Hh + h]);
            float c_new = fg * g_m[idx] + ig * gd;
            float h_new = og * tanhf(c_new);
            g_m[idx] = c_new;
            g_s[idx] = h_new;
            pack_elem(g_scP, 64, PO_SC, b, h, h_new);
            pack_elem(g_gAP, 64, PO_GA, b, Hh + h, h_new);
        }
        gridsync(nb);

        // ---------- P3: logits tiles via cp.async pipeline + partial softmax ----
        {
            // A quarter prefetch into slot q&1 (64KB each)
            auto prefA = [&](int q) {
                unsigned* dst = sm + (q & 1) * 16384;
#pragma unroll
                for (int i = 0; i < 16; i++) {
                    int j = tid + i * 256;                   // (kgl,mg,p,lane)
                    int l2 = j & 31, p = (j >> 5) & 1, mg = (j >> 6) & 3, kgl = j >> 8;
                    const unsigned* src = g_scP + (size_t)p * PO_SC
                        + (((size_t)mg * 64 + q * 16 + kgl) * 32 + l2) * 4;
                    cpa16(dst + (size_t)j * 4, src);
                }
            };
            // B kg prefetch into ring slot kg&3 (16KB each)
            auto prefB = [&](int kg) {
                unsigned* dst = sm + 32768 + (kg & 3) * 4096;
#pragma unroll
                for (int i = 0; i < 4; i++) {
                    int j = tid + i * 256;                   // (t2,ngl,lane)
                    int l2 = j & 31, ngl = (j >> 5) & 15, t2 = j >> 9;
                    int tile = t2 ? tile1 : tile0;
                    if (tile < NTILES) {
                        const unsigned* src = g_WyP
                            + (((size_t)(tile * 16 + ngl) * 64 + kg) * 32 + l2) * 4;
                        cpa16(dst + (size_t)j * 4, src);
                    }
                }
            };

            float acc[2][2][4][4];
#pragma unroll
            for (int ts = 0; ts < 2; ts++)
#pragma unroll
                for (int j = 0; j < 2; j++)
#pragma unroll
                    for (int g = 0; g < 4; g++)
#pragma unroll
                        for (int i = 0; i < 4; i++) acc[ts][j][g][i] = 0.f;

            // prologue: A0, B0, B1, B2
            prefA(0); CP_COMMIT();
            prefB(0); CP_COMMIT();
            prefB(1); CP_COMMIT();
            prefB(2); CP_COMMIT();

            const bool two = (tile1 < NTILES);
            for (int kg = 0; kg < 64; kg++) {
                CP_WAIT(2);
                __syncthreads();
                // issue next prefetches (always commit for uniform counting)
                if (kg + 3 < 64) prefB(kg + 3);
                CP_COMMIT();
                if ((kg & 15) == 12) {
                    if (kg + 4 < 64) prefA((kg + 4) >> 4);
                    CP_COMMIT();
                }

                const unsigned* sa = sm + ((kg >> 4) & 1) * 16384;
                const unsigned* sb = sm + 32768 + (kg & 3) * 4096;
                const int kgl = kg & 15;
                uint4 ah[4], al[4];
#pragma unroll
                for (int mg = 0; mg < 4; mg++) {
                    const unsigned* ap = sa + (((size_t)(kgl * 4 + mg) * 2) * 32 + lane) * 4;
                    ah[mg] = *(const uint4*)ap;
                    al[mg] = *(const uint4*)(ap + 128);
                }
                {
                    uint4 bb0 = *(const uint4*)(sb + (((size_t)(wid * 2)) * 32 + lane) * 4);
                    uint4 bb1 = *(const uint4*)(sb + (((size_t)(wid * 2 + 1)) * 32 + lane) * 4);
#pragma unroll
                    for (int mg = 0; mg < 4; mg++) {
                        mma16816(acc[0][0][mg], ah[mg].x, ah[mg].y, ah[mg].z, ah[mg].w, bb0.x, bb0.y);
                        mma16816(acc[0][0][mg], al[mg].x, al[mg].y, al[mg].z, al[mg].w, bb0.x, bb0.y);
                        mma16816(acc[0][0][mg], ah[mg].x, ah[mg].y, ah[mg].z, ah[mg].w, bb0.z, bb0.w);
                        mma16816(acc[0][1][mg], ah[mg].x, ah[mg].y, ah[mg].z, ah[mg].w, bb1.x, bb1.y);
                        mma16816(acc[0][1][mg], al[mg].x, al[mg].y, al[mg].z, al[mg].w, bb1.x, bb1.y);
                        mma16816(acc[0][1][mg], ah[mg].x, ah[mg].y, ah[mg].z, ah[mg].w, bb1.z, bb1.w);
                    }
                }
                if (two) {
                    uint4 bb0 = *(const uint4*)(sb + (((size_t)(16 + wid * 2)) * 32 + lane) * 4);
                    uint4 bb1 = *(const uint4*)(sb + (((size_t)(16 + wid * 2 + 1)) * 32 + lane) * 4);
#pragma unroll
                    for (int mg = 0; mg < 4; mg++) {
                        mma16816(acc[1][0][mg], ah[mg].x, ah[mg].y, ah[mg].z, ah[mg].w, bb0.x, bb0.y);
                        mma16816(acc[1][0][mg], al[mg].x, al[mg].y, al[mg].z, al[mg].w, bb0.x, bb0.y);
                        mma16816(acc[1][0][mg], ah[mg].x, ah[mg].y, ah[mg].z, ah[mg].w, bb0.z, bb0.w);
                        mma16816(acc[1][1][mg], ah[mg].x, ah[mg].y, ah[mg].z, ah[mg].w, bb1.x, bb1.y);
                        mma16816(acc[1][1][mg], al[mg].x, al[mg].y, al[mg].z, al[mg].w, bb1.x, bb1.y);
                        mma16816(acc[1][1][mg], ah[mg].x, ah[mg].y, ah[mg].z, ah[mg].w, bb1.z, bb1.w);
                    }
                }
            }
            CP_WAIT(0);
            __syncthreads();

            // epilogue per tile: write logits + row partials (reuse sm as float buf)
            float* sb = (float*)sm;
            const int r = lane >> 2, c = (lane & 3) * 2;
#pragma unroll
            for (int ts = 0; ts < 2; ts++) {
                int tile = ts ? tile1 : tile0;
                if (tile >= NTILES) break;
                __syncthreads();
#pragma unroll
                for (int j = 0; j < 2; j++) {
                    int ccol = wid * 16 + j * 8 + c;
#pragma unroll
                    for (int mg = 0; mg < 4; mg++) {
                        int m0 = mg * 16 + r;
                        float v0 = acc[ts][j][mg][0], v1 = acc[ts][j][mg][1];
                        float v2 = acc[ts][j][mg][2], v3 = acc[ts][j][mg][3];
                        sb[m0 * 132 + ccol] = v0;       sb[m0 * 132 + ccol + 1] = v1;
                        sb[(m0 + 8) * 132 + ccol] = v2; sb[(m0 + 8) * 132 + ccol + 1] = v3;
                        size_t g = (size_t)m0 * Vv + (size_t)tile * 128 + ccol;
                        *(float2*)&g_logits[g] = make_float2(v0, v1);
                        *(float2*)&g_logits[g + (size_t)8 * Vv] = make_float2(v2, v3);
                    }
                }
                __syncthreads();
                int row = tid >> 2, seg = tid & 3;
                float mx2 = -1e30f;
#pragma unroll 8
                for (int i = 0; i < 32; i++) mx2 = fmaxf(mx2, sb[row * 132 + seg + i * 4]);
                mx2 = fmaxf(mx2, __shfl_xor_sync(0xffffffffu, mx2, 1));
                mx2 = fmaxf(mx2, __shfl_xor_sync(0xffffffffu, mx2, 2));
                float sm2 = 0.f;
#pragma unroll 8
                for (int i = 0; i < 32; i++) sm2 += __expf(sb[row * 132 + seg + i * 4] - mx2);
                sm2 += __shfl_xor_sync(0xffffffffu, sm2, 1);
                sm2 += __shfl_xor_sync(0xffffffffu, sm2, 2);
                if (seg == 0) { g_pmax[tile * 64 + row] = mx2; g_psum[tile * 64 + row] = sm2; }
            }
        }
        gridsync(nb);
    }

    // final scatter for t = Tt-1
    if (bid >= Bb && bid - Bb < Bb) smfinal_body(bid - Bb, Tt - 1, out, s_red, tid);
}

// ---------------- launch -------------------------------------------------------
extern "C" void kernel_launch(void* const* d_in, const int* in_sizes, int n_in,
                              void* d_out, int out_size) {
    const int*   mr    = (const int*)d_in[0];
    const int*   ref   = (const int*)d_in[1];
    const int*   lens  = (const int*)d_in[2];
    const float* emb   = (const float*)d_in[3];
    const float* Wih_e = (const float*)d_in[4];
    const float* Whh_e = (const float*)d_in[5];
    const float* Wih_d = (const float*)d_in[6];
    const float* Whh_d = (const float*)d_in[7];
    const float* Wy    = (const float*)d_in[8];
    const float* Ws    = (const float*)d_in[9];
    const float* Wa1   = (const float*)d_in[10];
    const float* Wa2   = (const float*)d_in[11];
    float* out = (float*)d_out;

    float *p_Xih, *p_Gpre, *p_M12;
    unsigned *p_WyP, *p_GcatP, *p_WhhEP, *p_WihEP, *p_WsTP, *p_M1P, *p_WihdA;
    unsigned *p_xP, *p_tgtP;
    cudaGetSymbolAddress((void**)&p_Xih,    g_Xih);
    cudaGetSymbolAddress((void**)&p_Gpre,   g_Gpre);
    cudaGetSymbolAddress((void**)&p_M12,    g_M12);
    cudaGetSymbolAddress((void**)&p_WyP,    g_WyP);
    cudaGetSymbolAddress((void**)&p_GcatP,  g_GcatP);
    cudaGetSymbolAddress((void**)&p_WhhEP,  g_WhhEP);
    cudaGetSymbolAddress((void**)&p_WihEP,  g_WihEP);
    cudaGetSymbolAddress((void**)&p_WsTP,   g_WsTP);
    cudaGetSymbolAddress((void**)&p_M1P,    g_M1P);
    cudaGetSymbolAddress((void**)&p_WihdA,  g_WihdA);
    cudaGetSymbolAddress((void**)&p_xP,     g_xP);
    cudaGetSymbolAddress((void**)&p_tgtP,   g_tgtP);

    cudaFuncSetAttribute(k_decoder, cudaFuncAttributeMaxDynamicSharedMemorySize, 196608);

    // ---- prep ----
    k_sort<<<1, 1>>>(lens);
    k_gather_x<<<(Ss * Bb * Ee) / 256, 256>>>(mr, emb);
    k_gather_tgt<<<(Tt * Bb * Ee) / 256, 256>>>(ref, emb);
    k_init<<<128, 256>>>();

    // weight packs
    k_packB<<<32000, 256>>>(Wy, 1024, 1, Wy, 0, 0, 1 << 28, p_WyP, 64);
    k_packB<<<1024, 256>>>(Whh_e, 512, 1, Whh_e, 0, 0, 1 << 28, p_WhhEP, 32);
    k_packB<<<1024, 256>>>(Wih_e, 512, 1, Wih_e, 0, 0, 1 << 28, p_WihEP, 32);
    k_packB<<<512, 256>>>(Ws, 1, 1024, Ws, 0, 0, 1 << 28, p_WsTP, 32);   // Ws^T
    k_packAw<<<4096, 256>>>(Wih_d, p_WihdA, 32, PO_WIHD);

    // M12 = Wih_d @ Ws  [2048 x 1024]
    mma_gemm<<<dim3(16, 32), 256>>>(p_WihdA, PO_WIHD, p_WsTP, nullptr, 0, p_M12, KD, 32);
    k_packB<<<1024, 256>>>(p_M12, 1024, 1, p_M12, 0, 0, 1 << 28, p_M1P, 32);
    k_packB<<<2048, 256>>>(p_M12 + 512, 1024, 1, Whh_d, 512, 1, 512, p_GcatP, 64);

    // Xih = x @ W_ih_enc^T  [8192 x 2048]
    mma_gemm<<<dim3(32, 128), 256>>>(p_xP, PO_X, p_WihEP, nullptr, 0, p_Xih, G4, 32);
    // Gpre = tgt @ M1^T  [3072 x 2048]
    mma_gemm<<<dim3(32, 48), 256>>>(p_tgtP, PO_TGT, p_M1P, nullptr, 0, p_Gpre, G4, 32);

    // ---- encoder (persistent) ----
    k_encoder<<<128, 256>>>();

    k_att1<<<(Bb * Ss) / 8, 256>>>(Wa1);

    // ---- decoder (single persistent kernel) ----
    k_decoder<<<DECB, 256, 196608>>>(Wa2, lens, out);
}